// round 14
// baseline (speedup 1.0000x reference)
#include <cuda_runtime.h>
#include <cuda_bf16.h>
#include <stdint.h>
#include <math.h>

// Problem constants
#define BB   16
#define CC   256
#define NN   1024
#define HID  512
#define KNN  9
#define MTOT (BB*NN)   // 16384

// smem strides (u32 words), % 32 == 8 -> conflict-free fragment LDS
#define SA 136
#define SB 72

// GEMM smem sub-buffer sizes (bytes); one STAGE each, two stages per kernel
#define BF_AH (8*SA*4)      // 4352
#define BF_AB (2*BF_AH)     // Ah+Al
#define BF_BH (8*SB*4)      // 2304
#define BF_STG (BF_AB + 2*BF_BH)           // 13312  (split-bf16 stage)
#define TF_A (16*SA*4)      // 8704
#define TF_STG (TF_A + 16*SB*4)            // 13312  (tf32 stage)

// ---------------- scratch (static device globals; no allocations) ----------
__device__ float g_h   [(size_t)MTOT*CC];       // node-major h
__device__ float g_x2  [MTOT];                  // row squared norms
__device__ float g_dist[(size_t)BB*NN*NN];      // per-batch distance matrices
__device__ int   g_idx [MTOT*KNN];              // knn indices (batch-local)
__device__ float g_m   [(size_t)MTOT*2*CC];     // interleaved [h, maxdiff]
__device__ float g_g   [(size_t)MTOT*HID];      // post-GELU activations

// ---------------------------------------------------------------------------
// mma helpers
__device__ __forceinline__ uint32_t f2tf32(float f){
    uint32_t u; asm("cvt.rna.tf32.f32 %0, %1;" : "=r"(u) : "f"(f)); return u;
}
__device__ __forceinline__ void mma_tf32(float* c,
    uint32_t a0, uint32_t a1, uint32_t a2, uint32_t a3, uint32_t b0, uint32_t b1)
{
    asm volatile("mma.sync.aligned.m16n8k8.row.col.f32.tf32.tf32.f32 "
        "{%0,%1,%2,%3}, {%4,%5,%6,%7}, {%8,%9}, {%0,%1,%2,%3};"
        : "+f"(c[0]), "+f"(c[1]), "+f"(c[2]), "+f"(c[3])
        : "r"(a0), "r"(a1), "r"(a2), "r"(a3), "r"(b0), "r"(b1));
}
__device__ __forceinline__ void mma_bf16(float* c,
    uint32_t a0, uint32_t a1, uint32_t a2, uint32_t a3, uint32_t b0, uint32_t b1)
{
    asm volatile("mma.sync.aligned.m16n8k16.row.col.f32.bf16.bf16.f32 "
        "{%0,%1,%2,%3}, {%4,%5,%6,%7}, {%8,%9}, {%0,%1,%2,%3};"
        : "+f"(c[0]), "+f"(c[1]), "+f"(c[2]), "+f"(c[3])
        : "r"(a0), "r"(a1), "r"(a2), "r"(a3), "r"(b0), "r"(b1));
}

// split two floats (consecutive k) into packed bf16x2 hi and lo words
__device__ __forceinline__ void splitpack(float x, float y, uint32_t& h, uint32_t& l){
    __nv_bfloat16 hx = __float2bfloat16(x);
    __nv_bfloat16 hy = __float2bfloat16(y);
    float rx = x - __bfloat162float(hx);
    float ry = y - __bfloat162float(hy);
    __nv_bfloat16 lx = __float2bfloat16(rx);
    __nv_bfloat16 ly = __float2bfloat16(ry);
    uint16_t hxb = *(uint16_t*)&hx, hyb = *(uint16_t*)&hy;
    uint16_t lxb = *(uint16_t*)&lx, lyb = *(uint16_t*)&ly;
    h = ((uint32_t)hyb << 16) | hxb;
    l = ((uint32_t)lyb << 16) | lxb;
}

// store one split slab (A 8 values + B 4 values already in regs) into a stage
__device__ __forceinline__ void bfs_store_stage(char* stg, int am, int ak2,
    int bn, int bk2, const float4& a4a, const float4& a4b, const float4& b4)
{
    uint32_t* Ah = (uint32_t*)stg;
    uint32_t* Al = (uint32_t*)(stg + BF_AH);
    uint32_t* Bh = (uint32_t*)(stg + BF_AB);
    uint32_t* Bl = (uint32_t*)(stg + BF_AB + BF_BH);
    uint32_t h0,l0,h1,l1,h2,l2,h3,l3;
    splitpack(a4a.x, a4a.y, h0, l0);
    splitpack(a4a.z, a4a.w, h1, l1);
    splitpack(a4b.x, a4b.y, h2, l2);
    splitpack(a4b.z, a4b.w, h3, l3);
    Ah[(ak2+0)*SA + am] = h0; Al[(ak2+0)*SA + am] = l0;
    Ah[(ak2+1)*SA + am] = h1; Al[(ak2+1)*SA + am] = l1;
    Ah[(ak2+2)*SA + am] = h2; Al[(ak2+2)*SA + am] = l2;
    Ah[(ak2+3)*SA + am] = h3; Al[(ak2+3)*SA + am] = l3;
    uint32_t bh0,bl0,bh1,bl1;
    splitpack(b4.x, b4.y, bh0, bl0);
    splitpack(b4.z, b4.w, bh1, bl1);
    Bh[(bk2+0)*SB + bn] = bh0; Bl[(bk2+0)*SB + bn] = bl0;
    Bh[(bk2+1)*SB + bn] = bh1; Bl[(bk2+1)*SB + bn] = bl1;
}

// fragment load + 3-pass mma from a stage
__device__ __forceinline__ void bfs_mma_stage(const char* stg,
    int wm, int wn, int gid, int tig, float acc[2][4][4])
{
    const uint32_t* Ah = (const uint32_t*)stg;
    const uint32_t* Al = (const uint32_t*)(stg + BF_AH);
    const uint32_t* Bh = (const uint32_t*)(stg + BF_AB);
    const uint32_t* Bl = (const uint32_t*)(stg + BF_AB + BF_BH);
    uint32_t ahf[2][4], alf[2][4], bhf[4][2], blf[4][2];
#pragma unroll
    for (int mi = 0; mi < 2; mi++) {
        int mo = wm + mi*16 + gid;
        ahf[mi][0] = Ah[ tig   *SA + mo];
        ahf[mi][1] = Ah[ tig   *SA + mo + 8];
        ahf[mi][2] = Ah[(tig+4)*SA + mo];
        ahf[mi][3] = Ah[(tig+4)*SA + mo + 8];
        alf[mi][0] = Al[ tig   *SA + mo];
        alf[mi][1] = Al[ tig   *SA + mo + 8];
        alf[mi][2] = Al[(tig+4)*SA + mo];
        alf[mi][3] = Al[(tig+4)*SA + mo + 8];
    }
#pragma unroll
    for (int ni = 0; ni < 4; ni++) {
        int no = wn + ni*8 + gid;
        bhf[ni][0] = Bh[ tig   *SB + no];
        bhf[ni][1] = Bh[(tig+4)*SB + no];
        blf[ni][0] = Bl[ tig   *SB + no];
        blf[ni][1] = Bl[(tig+4)*SB + no];
    }
#pragma unroll
    for (int mi = 0; mi < 2; mi++)
#pragma unroll
        for (int ni = 0; ni < 4; ni++) {
            mma_bf16(acc[mi][ni], ahf[mi][0], ahf[mi][1], ahf[mi][2], ahf[mi][3],
                     bhf[ni][0], bhf[ni][1]);
            mma_bf16(acc[mi][ni], ahf[mi][0], ahf[mi][1], ahf[mi][2], ahf[mi][3],
                     blf[ni][0], blf[ni][1]);
            mma_bf16(acc[mi][ni], alf[mi][0], alf[mi][1], alf[mi][2], alf[mi][3],
                     bhf[ni][0], bhf[ni][1]);
        }
}

// ---------------------------------------------------------------------------
// Split-bf16 (hi+lo, 3-pass) GEMM core: 2-stage smem, ONE sync per slab.
// Block tile 128x64, 256 threads, 8 warps x (32x32). A/B row-major float.
template<int K>
__device__ __forceinline__ void bfs_gemm_tile(
    const float* __restrict__ A, const float* __restrict__ B,
    char* sbuf, float acc[2][4][4], int tid)
{
    const int lane = tid & 31, w = tid >> 5;
    const int gid = lane >> 2, tig = lane & 3;
    const int wm = (w & 3) * 32, wn = (w >> 2) * 32;
    const int am = tid >> 1, ak2 = (tid & 1) * 4;
    const int bn = tid >> 2, bk2 = (tid & 3) * 2;

    const float* Ap = A + (size_t)am*K + ak2*2;
    const float* Bp = B + (size_t)bn*K + bk2*2;
    float4 a4a = *(const float4*)(Ap);
    float4 a4b = *(const float4*)(Ap + 4);
    float4 b4  = *(const float4*)(Bp);

    bfs_store_stage(sbuf, am, ak2, bn, bk2, a4a, a4b, b4);   // slab 0 -> stage 0
    __syncthreads();

    for (int k0 = 0; k0 < K; k0 += 16) {
        const int st = (k0 >> 4) & 1;
        const bool more = (k0 + 16 < K);
        if (more) {
            a4a = *(const float4*)(Ap + k0 + 16);
            a4b = *(const float4*)(Ap + k0 + 20);
            b4  = *(const float4*)(Bp + k0 + 16);
        }
        bfs_mma_stage(sbuf + st*BF_STG, wm, wn, gid, tig, acc);
        if (more)
            bfs_store_stage(sbuf + (st^1)*BF_STG, am, ak2, bn, bk2, a4a, a4b, b4);
        __syncthreads();
    }
}

// fc1 variant: A read DIRECTLY from x (B,C,N) with transposed addressing.
__device__ __forceinline__ void bfs_gemm_fc1(
    const float* __restrict__ x, int r0,
    const float* __restrict__ B,
    char* sbuf, float acc[2][4][4], int tid)
{
    const int K = CC;
    const int lane = tid & 31, w = tid >> 5;
    const int gid = lane >> 2, tig = lane & 3;
    const int wm = (w & 3) * 32, wn = (w >> 2) * 32;
    const int am = tid >> 1, ak2 = (tid & 1) * 4;
    const int bn = tid >> 2, bk2 = (tid & 3) * 2;

    const int bb = r0 >> 10, n0l = r0 & 1023;
    const float* Ap = x + (size_t)bb*CC*NN + n0l + am;
    const float* Bp = B + (size_t)bn*K + bk2*2;

    float a8[8];
#pragma unroll
    for (int i = 0; i < 8; i++) a8[i] = Ap[(size_t)(ak2*2 + i)*NN];
    float4 b4 = *(const float4*)(Bp);
    float4 a4a, a4b;
    a4a.x=a8[0]; a4a.y=a8[1]; a4a.z=a8[2]; a4a.w=a8[3];
    a4b.x=a8[4]; a4b.y=a8[5]; a4b.z=a8[6]; a4b.w=a8[7];

    bfs_store_stage(sbuf, am, ak2, bn, bk2, a4a, a4b, b4);
    __syncthreads();

    for (int k0 = 0; k0 < K; k0 += 16) {
        const int st = (k0 >> 4) & 1;
        const bool more = (k0 + 16 < K);
        if (more) {
#pragma unroll
            for (int i = 0; i < 8; i++)
                a8[i] = Ap[(size_t)(k0 + 16 + ak2*2 + i)*NN];
            b4 = *(const float4*)(Bp + k0 + 16);
            a4a.x=a8[0]; a4a.y=a8[1]; a4a.z=a8[2]; a4a.w=a8[3];
            a4b.x=a8[4]; a4b.y=a8[5]; a4b.z=a8[6]; a4b.w=a8[7];
        }
        bfs_mma_stage(sbuf + st*BF_STG, wm, wn, gid, tig, acc);
        if (more)
            bfs_store_stage(sbuf + (st^1)*BF_STG, am, ak2, bn, bk2, a4a, a4b, b4);
        __syncthreads();
    }
}

// ---------------------------------------------------------------------------
// tf32 single-pass GEMM core: 2-stage smem, ONE sync per slab.
__device__ __forceinline__ void tf32_store_stage(char* stg, int am, int ak,
    int bn, int bk, const float4& a4a, const float4& a4b, const float4& b4)
{
    uint32_t* Ask = (uint32_t*)stg;
    uint32_t* Bsk = (uint32_t*)(stg + TF_A);
    Ask[(ak+0)*SA + am] = f2tf32(a4a.x);
    Ask[(ak+1)*SA + am] = f2tf32(a4a.y);
    Ask[(ak+2)*SA + am] = f2tf32(a4a.z);
    Ask[(ak+3)*SA + am] = f2tf32(a4a.w);
    Ask[(ak+4)*SA + am] = f2tf32(a4b.x);
    Ask[(ak+5)*SA + am] = f2tf32(a4b.y);
    Ask[(ak+6)*SA + am] = f2tf32(a4b.z);
    Ask[(ak+7)*SA + am] = f2tf32(a4b.w);
    Bsk[(bk+0)*SB + bn] = f2tf32(b4.x);
    Bsk[(bk+1)*SB + bn] = f2tf32(b4.y);
    Bsk[(bk+2)*SB + bn] = f2tf32(b4.z);
    Bsk[(bk+3)*SB + bn] = f2tf32(b4.w);
}
__device__ __forceinline__ void tf32_mma_stage(const char* stg,
    int wm, int wn, int gid, int tig, float acc[2][4][4])
{
    const uint32_t* Ask = (const uint32_t*)stg;
    const uint32_t* Bsk = (const uint32_t*)(stg + TF_A);
#pragma unroll
    for (int ks = 0; ks < 16; ks += 8) {
        uint32_t af[2][4], bf[4][2];
#pragma unroll
        for (int mi = 0; mi < 2; mi++) {
            int mo = wm + mi*16 + gid;
            af[mi][0] = Ask[(ks+tig  )*SA + mo];
            af[mi][1] = Ask[(ks+tig  )*SA + mo + 8];
            af[mi][2] = Ask[(ks+tig+4)*SA + mo];
            af[mi][3] = Ask[(ks+tig+4)*SA + mo + 8];
        }
#pragma unroll
        for (int ni = 0; ni < 4; ni++) {
            int no = wn + ni*8 + gid;
            bf[ni][0] = Bsk[(ks+tig  )*SB + no];
            bf[ni][1] = Bsk[(ks+tig+4)*SB + no];
        }
#pragma unroll
        for (int mi = 0; mi < 2; mi++)
#pragma unroll
            for (int ni = 0; ni < 4; ni++)
                mma_tf32(acc[mi][ni], af[mi][0], af[mi][1], af[mi][2], af[mi][3],
                         bf[ni][0], bf[ni][1]);
    }
}
template<int K>
__device__ __forceinline__ void tf32_gemm_tile(
    const float* __restrict__ A, const float* __restrict__ B,
    char* sbuf, float acc[2][4][4], int tid)
{
    const int lane = tid & 31, w = tid >> 5;
    const int gid = lane >> 2, tig = lane & 3;
    const int wm = (w & 3) * 32, wn = (w >> 2) * 32;
    const int am = tid >> 1, ak = (tid & 1) * 8;
    const int bn = tid >> 2, bk = (tid & 3) * 4;

    const float* Ap = A + (size_t)am*K + ak;
    const float* Bp = B + (size_t)bn*K + bk;
    float4 a4a = *(const float4*)(Ap);
    float4 a4b = *(const float4*)(Ap + 4);
    float4 b4  = *(const float4*)(Bp);

    tf32_store_stage(sbuf, am, ak, bn, bk, a4a, a4b, b4);
    __syncthreads();

    for (int k0 = 0; k0 < K; k0 += 16) {
        const int st = (k0 >> 4) & 1;
        const bool more = (k0 + 16 < K);
        if (more) {
            a4a = *(const float4*)(Ap + k0 + 16);
            a4b = *(const float4*)(Ap + k0 + 20);
            b4  = *(const float4*)(Bp + k0 + 16);
        }
        tf32_mma_stage(sbuf + st*TF_STG, wm, wn, gid, tig, acc);
        if (more)
            tf32_store_stage(sbuf + (st^1)*TF_STG, am, ak, bn, bk, a4a, a4b, b4);
        __syncthreads();
    }
}

// ---------------------------------------------------------------------------
// Kernel 1 (split-bf16): h = BN1(fc1_w @ xT + fc1_b), node-major output.
// Grid: (c-blocks, r-blocks) -> same-A blocks launch-adjacent (L2 reuse).
__global__ void __launch_bounds__(256) fc1_kernel(
    const float* __restrict__ x,
    const float* __restrict__ w, const float* __restrict__ bias,
    const float* __restrict__ bg, const float* __restrict__ bbta,
    const float* __restrict__ bm, const float* __restrict__ bv)
{
    __shared__ __align__(16) char sbuf[2*BF_STG];
    const int r0 = blockIdx.y * 128;
    const int c0 = blockIdx.x * 64;
    const int tid = threadIdx.x;

    float acc[2][4][4];
#pragma unroll
    for (int mi = 0; mi < 2; mi++)
#pragma unroll
        for (int ni = 0; ni < 4; ni++)
#pragma unroll
            for (int q = 0; q < 4; q++) acc[mi][ni][q] = 0.f;

    bfs_gemm_fc1(x, r0, w + (size_t)c0*CC, sbuf, acc, tid);

    const int lane = tid & 31, wp = tid >> 5;
    const int gid = lane >> 2, tig = lane & 3;
    const int wm = (wp & 3) * 32, wn = (wp >> 2) * 32;
#pragma unroll
    for (int ni = 0; ni < 4; ni++) {
        int col = c0 + wn + ni*8 + 2*tig;
        float sca = bg[col]   * rsqrtf(bv[col]   + 1e-5f);
        float scb = bg[col+1] * rsqrtf(bv[col+1] + 1e-5f);
        float sha = bbta[col]   - bm[col]  *sca;
        float shb = bbta[col+1] - bm[col+1]*scb;
        float bia = bias[col], bib = bias[col+1];
#pragma unroll
        for (int mi = 0; mi < 2; mi++) {
            int r_lo = r0 + wm + mi*16 + gid;
#pragma unroll
            for (int h = 0; h < 2; h++) {
                int r = r_lo + h*8;
                float2 v2;
                v2.x = (acc[mi][ni][2*h]   + bia)*sca + sha;
                v2.y = (acc[mi][ni][2*h+1] + bib)*scb + shb;
                *(float2*)(g_h + (size_t)r*CC + col) = v2;
            }
        }
    }
}

// ---------------------------------------------------------------------------
// Kernel 2: row squared norms of h (MLP=8 batched loads, same fma order).
__global__ void x2_kernel()
{
    int warp = (blockIdx.x*blockDim.x + threadIdx.x) >> 5;
    int lane = threadIdx.x & 31;
    if (warp >= MTOT) return;
    const float* r = g_h + (size_t)warp*CC;
    float v[8];
#pragma unroll
    for (int i = 0; i < 8; i++) v[i] = r[lane + i*32];
    float s = 0.f;
#pragma unroll
    for (int i = 0; i < 8; i++) s = fmaf(v[i], v[i], s);
#pragma unroll
    for (int o = 16; o; o >>= 1) s += __shfl_xor_sync(0xffffffffu, s, o);
    if (!lane) g_x2[warp] = s;
}

// ---------------------------------------------------------------------------
// Kernel 3 (split-bf16, symmetric): dist[b][n][m] = x2[n]+x2[m]-2<h_n,h_m>.
// 128(n) x 64(m) tiles; compute only blocks with bj >= 2*bi; fill the rest
// via guarded transpose writes. GEMM stages aliased with transpose stage.
__global__ void __launch_bounds__(256) dist_kernel()
{
    __shared__ __align__(16) char sbuf[64*129*4 > 2*BF_STG ? 64*129*4 : 2*BF_STG];
    float (*Os)[129] = (float(*)[129])sbuf;
    const int b = blockIdx.z;
    int t = blockIdx.x;
    int bi = 0;
    while (t >= 16 - 2*bi) { t -= 16 - 2*bi; bi++; }
    const int bj = 2*bi + t;
    const int n0 = bi * 128;
    const int m0 = bj * 64;
    const int tid = threadIdx.x;
    const float* hb = g_h + (size_t)b*NN*CC;

    float acc[2][4][4];
#pragma unroll
    for (int mi = 0; mi < 2; mi++)
#pragma unroll
        for (int ni = 0; ni < 4; ni++)
#pragma unroll
            for (int q = 0; q < 4; q++) acc[mi][ni][q] = 0.f;

    bfs_gemm_tile<CC>(hb + (size_t)n0*CC, hb + (size_t)m0*CC, sbuf, acc, tid);

    float* db = g_dist + (size_t)b*NN*NN;
    const int lane = tid & 31, wp = tid >> 5;
    const int gid = lane >> 2, tig = lane & 3;
    const int wm = (wp & 3) * 32, wn = (wp >> 2) * 32;
#pragma unroll
    for (int ni = 0; ni < 4; ni++) {
        int cl = wn + ni*8 + 2*tig;
        float xa = g_x2[b*NN + m0 + cl];
        float xb2 = g_x2[b*NN + m0 + cl + 1];
#pragma unroll
        for (int mi = 0; mi < 2; mi++) {
            int rl_lo = wm + mi*16 + gid;
#pragma unroll
            for (int h = 0; h < 2; h++) {
                int rl = rl_lo + h*8;
                int n = n0 + rl;
                float xn = g_x2[b*NN + n];
                float2 v2;
                v2.x = xn + xa  - 2.f*acc[mi][ni][2*h];
                v2.y = xn + xb2 - 2.f*acc[mi][ni][2*h+1];
                *(float2*)(db + (size_t)n*NN + m0 + cl) = v2;    // direct tile
                Os[cl][rl]   = v2.x;                              // transpose stage
                Os[cl+1][rl] = v2.y;
            }
        }
    }
    __syncthreads();
    // transpose write: dist[m][n], skip positions already direct-covered
#pragma unroll
    for (int it = 0; it < 32; it++) {
        int e = tid + it*256;     // 8192 elements
        int il = e & 127;         // local n (fastest -> coalesced)
        int jl = e >> 7;          // local m
        int r = m0 + jl;
        int c = n0 + il;
        if ((c >> 6) < 2*(r >> 7))
            db[(size_t)r*NN + c] = Os[jl][il];
    }
}

// ---------------------------------------------------------------------------
// Kernel 4: top-9 smallest per row (tie -> lower index). Warp per row,
// per-lane top-2 cache + lazy bitmask removal + REDUX reductions.
__global__ void __launch_bounds__(256) topk_kernel()
{
    const int w = threadIdx.x >> 5, lane = threadIdx.x & 31;
    const int row = blockIdx.x*8 + w;                // 8 warps/block
    const float* d = g_dist + (size_t)row * NN;

    unsigned u[32];
#pragma unroll
    for (int j = 0; j < 32; j++) {
        unsigned t = __float_as_uint(d[lane + j*32]);
        u[j] = (t & 0x80000000u) ? ~t : (t | 0x80000000u);   // monotonic map
    }

    unsigned m1 = u[0], m2 = 0xffffffffu;
    int i1 = 0, i2 = 0;
#pragma unroll
    for (int j = 1; j < 32; j++) {
        if (u[j] < m1)      { m2 = m1; i2 = i1; m1 = u[j]; i1 = j; }
        else if (u[j] < m2) { m2 = u[j]; i2 = j; }
    }
    bool have2 = true;
    unsigned removed = 0;

    for (int kp = 0; kp < KNN; kp++) {
        unsigned gm = __reduce_min_sync(0xffffffffu, m1);
        unsigned cand = (m1 == gm) ? (unsigned)(lane + (i1 << 5)) : 0xffffffffu;
        int sidx = (int)__reduce_min_sync(0xffffffffu, cand);
        if (!lane) g_idx[row*KNN + kp] = sidx;
        if ((sidx & 31) == lane) {
            removed |= 1u << i1;
            if (have2) { m1 = m2; i1 = i2; have2 = false; }
            else {
                m1 = 0xffffffffu; m2 = 0xffffffffu; i1 = 0; i2 = 0;
#pragma unroll
                for (int j = 0; j < 32; j++) {
                    unsigned uu = ((removed >> j) & 1u) ? 0xffffffffu : u[j];
                    if (uu < m1)      { m2 = m1; i2 = i1; m1 = uu; i1 = j; }
                    else if (uu < m2) { m2 = uu; i2 = j; }
                }
                have2 = true;
            }
        }
    }
}

// ---------------------------------------------------------------------------
// Kernel 5: MRConv + interleave (batched neighbor loads, same fmaxf order).
__global__ void mrconv_kernel()
{
    const int n = blockIdx.x, b = blockIdx.y, c = threadIdx.x;  // 256 threads
    const size_t rowb = (size_t)b*NN + n;
    __shared__ int sidx[KNN];
    if (c < KNN) sidx[c] = g_idx[rowb*KNN + c];
    __syncthreads();
    float v = g_h[rowb*CC + c];
    float nv[KNN];
#pragma unroll
    for (int j = 0; j < KNN; j++)
        nv[j] = g_h[((size_t)b*NN + sidx[j])*CC + c];
    float mx = -INFINITY;
#pragma unroll
    for (int j = 0; j < KNN; j++)
        mx = fmaxf(mx, nv[j] - v);
    float* mo = g_m + rowb*2*CC;
    mo[2*c]   = v;
    mo[2*c+1] = mx;
}

// ---------------------------------------------------------------------------
// Kernel 6 (tf32 mma): g = GELU(BN2(GBN(gc_w @ m + gc_b)))
// Grid: (c-blocks, r-blocks) for A-row L2 reuse.
__global__ void __launch_bounds__(256) gc_kernel(
    const float* __restrict__ w, const float* __restrict__ bias,
    const float* __restrict__ g1g, const float* __restrict__ g1b,
    const float* __restrict__ g1m, const float* __restrict__ g1v,
    const float* __restrict__ g2g, const float* __restrict__ g2b,
    const float* __restrict__ g2m, const float* __restrict__ g2v)
{
    __shared__ __align__(16) char sbuf[2*TF_STG];
    const int r0 = blockIdx.y * 128;
    const int c0 = blockIdx.x * 64;
    const int tid = threadIdx.x;

    float acc[2][4][4];
#pragma unroll
    for (int mi = 0; mi < 2; mi++)
#pragma unroll
        for (int ni = 0; ni < 4; ni++)
#pragma unroll
            for (int q = 0; q < 4; q++) acc[mi][ni][q] = 0.f;

    tf32_gemm_tile<2*CC>(g_m + (size_t)r0*(2*CC), w + (size_t)c0*(2*CC), sbuf, acc, tid);

    const int lane = tid & 31, wp = tid >> 5;
    const int gid = lane >> 2, tig = lane & 3;
    const int wm = (wp & 3) * 32, wn = (wp >> 2) * 32;
#pragma unroll
    for (int ni = 0; ni < 4; ni++) {
        int col = c0 + wn + ni*8 + 2*tig;
        float s1a = g1g[col]   * rsqrtf(g1v[col]   + 1e-5f);
        float s1b = g1g[col+1] * rsqrtf(g1v[col+1] + 1e-5f);
        float t1a = g1b[col]   - g1m[col]  *s1a;
        float t1b = g1b[col+1] - g1m[col+1]*s1b;
        float s2a = g2g[col]   * rsqrtf(g2v[col]   + 1e-5f);
        float s2b = g2g[col+1] * rsqrtf(g2v[col+1] + 1e-5f);
        float t2a = g2b[col]   - g2m[col]  *s2a;
        float t2b = g2b[col+1] - g2m[col+1]*s2b;
        float bia = bias[col], bib = bias[col+1];
#pragma unroll
        for (int mi = 0; mi < 2; mi++) {
            int r_lo = r0 + wm + mi*16 + gid;
#pragma unroll
            for (int h = 0; h < 2; h++) {
                int r = r_lo + h*8;
                float ya = ((acc[mi][ni][2*h]   + bia)*s1a + t1a)*s2a + t2a;
                float yb = ((acc[mi][ni][2*h+1] + bib)*s1b + t1b)*s2b + t2b;
                ya = 0.5f * ya * (1.f + erff(ya * 0.70710678118654752440f));
                yb = 0.5f * yb * (1.f + erff(yb * 0.70710678118654752440f));
                float2 v2; v2.x = ya; v2.y = yb;
                *(float2*)(g_g + (size_t)r*HID + col) = v2;
            }
        }
    }
}

// ---------------------------------------------------------------------------
// Kernel 7 (tf32 mma): out = BN3(fc2_w @ g + fc2_b) + x, (B,C,N) layout via
// smem restage (aliased with GEMM stages) for coalesced transposed stores.
__global__ void __launch_bounds__(256) fc2_kernel(
    const float* __restrict__ w, const float* __restrict__ bias,
    const float* __restrict__ bg, const float* __restrict__ bbta,
    const float* __restrict__ bm, const float* __restrict__ bv,
    const float* __restrict__ x, float* __restrict__ out)
{
    __shared__ __align__(16) char sbuf[128*65*4];   // 33280 > 2*TF_STG
    float* Os = (float*)sbuf;
    const int r0 = blockIdx.y * 128;
    const int c0 = blockIdx.x * 64;
    const int tid = threadIdx.x;

    float acc[2][4][4];
#pragma unroll
    for (int mi = 0; mi < 2; mi++)
#pragma unroll
        for (int ni = 0; ni < 4; ni++)
#pragma unroll
            for (int q = 0; q < 4; q++) acc[mi][ni][q] = 0.f;

    tf32_gemm_tile<HID>(g_g + (size_t)r0*HID, w + (size_t)c0*HID, sbuf, acc, tid);
    __syncthreads();   // GEMM stages dead; safe to reuse as Os

    const int lane = tid & 31, wp = tid >> 5;
    const int gid = lane >> 2, tig = lane & 3;
    const int wm = (wp & 3) * 32, wn = (wp >> 2) * 32;
#pragma unroll
    for (int ni = 0; ni < 4; ni++) {
        int cl = wn + ni*8 + 2*tig;
        int col = c0 + cl;
        float sca = bg[col]   * rsqrtf(bv[col]   + 1e-5f);
        float scb = bg[col+1] * rsqrtf(bv[col+1] + 1e-5f);
        float sha = bbta[col]   - bm[col]  *sca;
        float shb = bbta[col+1] - bm[col+1]*scb;
        float bia = bias[col], bib = bias[col+1];
#pragma unroll
        for (int mi = 0; mi < 2; mi++) {
            int rl_lo = wm + mi*16 + gid;
#pragma unroll
            for (int h = 0; h < 2; h++) {
                int rl = rl_lo + h*8;
                Os[rl*65 + cl]     = (acc[mi][ni][2*h]   + bia)*sca + sha;
                Os[rl*65 + cl + 1] = (acc[mi][ni][2*h+1] + bib)*scb + shb;
            }
        }
    }
    __syncthreads();
    const int b = r0 >> 10;
    const int nbase = r0 & 1023;
#pragma unroll
    for (int it = 0; it < 32; it++) {
        int e = tid + it*256;     // 8192 elements
        int nl = e & 127;
        int cl = e >> 7;
        size_t o = (size_t)b*CC*NN + (size_t)(c0 + cl)*NN + (nbase + nl);
        out[o] = Os[nl*65 + cl] + x[o];
    }
}

// ---------------------------------------------------------------------------
extern "C" void kernel_launch(void* const* d_in, const int* in_sizes, int n_in,
                              void* d_out, int out_size)
{
    const float* x     = (const float*)d_in[0];
    const float* fc1_w = (const float*)d_in[1];
    const float* fc1_b = (const float*)d_in[2];
    const float* bn1_g = (const float*)d_in[3];
    const float* bn1_b = (const float*)d_in[4];
    const float* bn1_m = (const float*)d_in[5];
    const float* bn1_v = (const float*)d_in[6];
    const float* gc_w  = (const float*)d_in[7];
    const float* gc_b  = (const float*)d_in[8];
    const float* gbn_g = (const float*)d_in[9];
    const float* gbn_b = (const float*)d_in[10];
    const float* gbn_m = (const float*)d_in[11];
    const float* gbn_v = (const float*)d_in[12];
    const float* bn2_g = (const float*)d_in[13];
    const float* bn2_b = (const float*)d_in[14];
    const float* bn2_m = (const float*)d_in[15];
    const float* bn2_v = (const float*)d_in[16];
    const float* fc2_w = (const float*)d_in[17];
    const float* fc2_b = (const float*)d_in[18];
    const float* bn3_g = (const float*)d_in[19];
    const float* bn3_b = (const float*)d_in[20];
    const float* bn3_m = (const float*)d_in[21];
    const float* bn3_v = (const float*)d_in[22];
    float* out = (float*)d_out;

    // 1) fc1 + BN1 -> h (split-bf16, 2-stage pipeline, c-fastest grid)
    {
        dim3 grid(CC/64, MTOT/128);
        fc1_kernel<<<grid, 256>>>(x, fc1_w, fc1_b, bn1_g, bn1_b, bn1_m, bn1_v);
    }
    // 2) row norms
    x2_kernel<<<(MTOT*32)/256, 256>>>();
    // 3) pairwise distances (split-bf16, 2-stage pipeline, symmetric blocks)
    {
        dim3 grid(72, 1, BB);
        dist_kernel<<<grid, 256>>>();
    }
    // 4) top-9 nearest per node (warp per row, top-2 cache + REDUX)
    topk_kernel<<<MTOT/8, 256>>>();
    // 5) MRConv + interleave
    {
        dim3 grid(NN, BB);
        mrconv_kernel<<<grid, 256>>>();
    }
    // 6) gc + gbn + bn2 + GELU (tf32, 2-stage pipeline, c-fastest grid)
    {
        dim3 grid(HID/64, MTOT/128);
        gc_kernel<<<grid, 256>>>(gc_w, gc_b, gbn_g, gbn_b, gbn_m, gbn_v,
                                 bn2_g, bn2_b, bn2_m, bn2_v);
    }
    // 7) fc2 + bn3 + residual (tf32, 2-stage pipeline, c-fastest grid)
    {
        dim3 grid(CC/64, MTOT/128);
        fc2_kernel<<<grid, 256>>>(fc2_w, fc2_b, bn3_g, bn3_b, bn3_m, bn3_v, x, out);
    }
}

// round 15
// speedup vs baseline: 1.0258x; 1.0258x over previous
#include <cuda_runtime.h>
#include <cuda_bf16.h>
#include <stdint.h>
#include <math.h>

// Problem constants
#define BB   16
#define CC   256
#define NN   1024
#define HID  512
#define KNN  9
#define MTOT (BB*NN)   // 16384

// smem strides (u32 words), % 32 == 8 -> conflict-free fragment LDS
#define SA 136
#define SB 72

// GEMM smem sub-buffer sizes (bytes)
#define BF_AH (8*SA*4)      // 4352
#define BF_AB (2*BF_AH)     // Ah+Al
#define BF_BH (8*SB*4)      // 2304
#define BF_GEMM (BF_AB + 2*BF_BH)          // 13312  (split-bf16 core)
#define TF_A (16*SA*4)      // 8704
#define TF_B (16*SB*4)      // 4608
#define TF_GEMM (TF_A + TF_B)              // 13312  (tf32 core)

// ---------------- scratch (static device globals; no allocations) ----------
__device__ float g_h   [(size_t)MTOT*CC];       // node-major h
__device__ float g_x2  [MTOT];                  // row squared norms
__device__ float g_dist[(size_t)BB*NN*NN];      // per-batch distance matrices
__device__ int   g_idx [MTOT*KNN];              // knn indices (batch-local)
__device__ float g_m   [(size_t)MTOT*2*CC];     // interleaved [h, maxdiff]
__device__ float g_g   [(size_t)MTOT*HID];      // post-GELU activations

// ---------------------------------------------------------------------------
// mma helpers
__device__ __forceinline__ uint32_t f2tf32(float f){
    uint32_t u; asm("cvt.rna.tf32.f32 %0, %1;" : "=r"(u) : "f"(f)); return u;
}
__device__ __forceinline__ void mma_tf32(float* c,
    uint32_t a0, uint32_t a1, uint32_t a2, uint32_t a3, uint32_t b0, uint32_t b1)
{
    asm volatile("mma.sync.aligned.m16n8k8.row.col.f32.tf32.tf32.f32 "
        "{%0,%1,%2,%3}, {%4,%5,%6,%7}, {%8,%9}, {%0,%1,%2,%3};"
        : "+f"(c[0]), "+f"(c[1]), "+f"(c[2]), "+f"(c[3])
        : "r"(a0), "r"(a1), "r"(a2), "r"(a3), "r"(b0), "r"(b1));
}
__device__ __forceinline__ void mma_bf16(float* c,
    uint32_t a0, uint32_t a1, uint32_t a2, uint32_t a3, uint32_t b0, uint32_t b1)
{
    asm volatile("mma.sync.aligned.m16n8k16.row.col.f32.bf16.bf16.f32 "
        "{%0,%1,%2,%3}, {%4,%5,%6,%7}, {%8,%9}, {%0,%1,%2,%3};"
        : "+f"(c[0]), "+f"(c[1]), "+f"(c[2]), "+f"(c[3])
        : "r"(a0), "r"(a1), "r"(a2), "r"(a3), "r"(b0), "r"(b1));
}

// split two floats (consecutive k) into packed bf16x2 hi and lo words
__device__ __forceinline__ void splitpack(float x, float y, uint32_t& h, uint32_t& l){
    __nv_bfloat16 hx = __float2bfloat16(x);
    __nv_bfloat16 hy = __float2bfloat16(y);
    float rx = x - __bfloat162float(hx);
    float ry = y - __bfloat162float(hy);
    __nv_bfloat16 lx = __float2bfloat16(rx);
    __nv_bfloat16 ly = __float2bfloat16(ry);
    uint16_t hxb = *(uint16_t*)&hx, hyb = *(uint16_t*)&hy;
    uint16_t lxb = *(uint16_t*)&lx, lyb = *(uint16_t*)&ly;
    h = ((uint32_t)hyb << 16) | hxb;
    l = ((uint32_t)lyb << 16) | lxb;
}

// ---------------------------------------------------------------------------
// Split-bf16 (hi+lo, 3-pass) GEMM core, register-prefetch pipelined.
// Block tile 128x64, 256 threads, 8 warps x (32x32). A/B row-major float.
template<int K>
__device__ __forceinline__ void bfs_gemm_tile(
    const float* __restrict__ A, const float* __restrict__ B,
    uint32_t* Ah, uint32_t* Al, uint32_t* Bh, uint32_t* Bl,
    float acc[2][4][4], int tid)
{
    const int lane = tid & 31, w = tid >> 5;
    const int gid = lane >> 2, tig = lane & 3;
    const int wm = (w & 3) * 32, wn = (w >> 2) * 32;
    const int am = tid >> 1, ak2 = (tid & 1) * 4;  // A: 128 rows, 2 thr/row
    const int bn = tid >> 2, bk2 = (tid & 3) * 2;  // B: 64 rows, 4 thr/row

    const float* Ap = A + (size_t)am*K + ak2*2;
    const float* Bp = B + (size_t)bn*K + bk2*2;
    float4 a4a = *(const float4*)(Ap);
    float4 a4b = *(const float4*)(Ap + 4);
    float4 b4  = *(const float4*)(Bp);

    for (int k0 = 0; k0 < K; k0 += 16) {
        uint32_t h0,l0,h1,l1,h2,l2,h3,l3;
        splitpack(a4a.x, a4a.y, h0, l0);
        splitpack(a4a.z, a4a.w, h1, l1);
        splitpack(a4b.x, a4b.y, h2, l2);
        splitpack(a4b.z, a4b.w, h3, l3);
        Ah[(ak2+0)*SA + am] = h0; Al[(ak2+0)*SA + am] = l0;
        Ah[(ak2+1)*SA + am] = h1; Al[(ak2+1)*SA + am] = l1;
        Ah[(ak2+2)*SA + am] = h2; Al[(ak2+2)*SA + am] = l2;
        Ah[(ak2+3)*SA + am] = h3; Al[(ak2+3)*SA + am] = l3;
        uint32_t bh0,bl0,bh1,bl1;
        splitpack(b4.x, b4.y, bh0, bl0);
        splitpack(b4.z, b4.w, bh1, bl1);
        Bh[(bk2+0)*SB + bn] = bh0; Bl[(bk2+0)*SB + bn] = bl0;
        Bh[(bk2+1)*SB + bn] = bh1; Bl[(bk2+1)*SB + bn] = bl1;
        __syncthreads();
        if (k0 + 16 < K) {                       // prefetch next slab
            a4a = *(const float4*)(Ap + k0 + 16);
            a4b = *(const float4*)(Ap + k0 + 20);
            b4  = *(const float4*)(Bp + k0 + 16);
        }
        uint32_t ahf[2][4], alf[2][4], bhf[4][2], blf[4][2];
#pragma unroll
        for (int mi = 0; mi < 2; mi++) {
            int mo = wm + mi*16 + gid;
            ahf[mi][0] = Ah[ tig   *SA + mo];
            ahf[mi][1] = Ah[ tig   *SA + mo + 8];
            ahf[mi][2] = Ah[(tig+4)*SA + mo];
            ahf[mi][3] = Ah[(tig+4)*SA + mo + 8];
            alf[mi][0] = Al[ tig   *SA + mo];
            alf[mi][1] = Al[ tig   *SA + mo + 8];
            alf[mi][2] = Al[(tig+4)*SA + mo];
            alf[mi][3] = Al[(tig+4)*SA + mo + 8];
        }
#pragma unroll
        for (int ni = 0; ni < 4; ni++) {
            int no = wn + ni*8 + gid;
            bhf[ni][0] = Bh[ tig   *SB + no];
            bhf[ni][1] = Bh[(tig+4)*SB + no];
            blf[ni][0] = Bl[ tig   *SB + no];
            blf[ni][1] = Bl[(tig+4)*SB + no];
        }
#pragma unroll
        for (int mi = 0; mi < 2; mi++)
#pragma unroll
            for (int ni = 0; ni < 4; ni++) {
                mma_bf16(acc[mi][ni], ahf[mi][0], ahf[mi][1], ahf[mi][2], ahf[mi][3],
                         bhf[ni][0], bhf[ni][1]);
                mma_bf16(acc[mi][ni], ahf[mi][0], ahf[mi][1], ahf[mi][2], ahf[mi][3],
                         blf[ni][0], blf[ni][1]);
                mma_bf16(acc[mi][ni], alf[mi][0], alf[mi][1], alf[mi][2], alf[mi][3],
                         bhf[ni][0], bhf[ni][1]);
            }
        __syncthreads();
    }
}

// ---------------------------------------------------------------------------
// fc1 variant: A is read DIRECTLY from x (B,C,N) with transposed addressing.
__device__ __forceinline__ void bfs_gemm_fc1(
    const float* __restrict__ x, int r0,
    const float* __restrict__ B,
    uint32_t* Ah, uint32_t* Al, uint32_t* Bh, uint32_t* Bl,
    float acc[2][4][4], int tid)
{
    const int K = CC;
    const int lane = tid & 31, w = tid >> 5;
    const int gid = lane >> 2, tig = lane & 3;
    const int wm = (w & 3) * 32, wn = (w >> 2) * 32;
    const int am = tid >> 1, ak2 = (tid & 1) * 4;
    const int bn = tid >> 2, bk2 = (tid & 3) * 2;

    const int bb = r0 >> 10, n0l = r0 & 1023;
    const float* Ap = x + (size_t)bb*CC*NN + n0l + am;
    const float* Bp = B + (size_t)bn*K + bk2*2;

    float a8[8];
#pragma unroll
    for (int i = 0; i < 8; i++) a8[i] = Ap[(size_t)(ak2*2 + i)*NN];
    float4 b4 = *(const float4*)(Bp);

    for (int k0 = 0; k0 < K; k0 += 16) {
        uint32_t h0,l0,h1,l1,h2,l2,h3,l3;
        splitpack(a8[0], a8[1], h0, l0);
        splitpack(a8[2], a8[3], h1, l1);
        splitpack(a8[4], a8[5], h2, l2);
        splitpack(a8[6], a8[7], h3, l3);
        Ah[(ak2+0)*SA + am] = h0; Al[(ak2+0)*SA + am] = l0;
        Ah[(ak2+1)*SA + am] = h1; Al[(ak2+1)*SA + am] = l1;
        Ah[(ak2+2)*SA + am] = h2; Al[(ak2+2)*SA + am] = l2;
        Ah[(ak2+3)*SA + am] = h3; Al[(ak2+3)*SA + am] = l3;
        uint32_t bh0,bl0,bh1,bl1;
        splitpack(b4.x, b4.y, bh0, bl0);
        splitpack(b4.z, b4.w, bh1, bl1);
        Bh[(bk2+0)*SB + bn] = bh0; Bl[(bk2+0)*SB + bn] = bl0;
        Bh[(bk2+1)*SB + bn] = bh1; Bl[(bk2+1)*SB + bn] = bl1;
        __syncthreads();
        if (k0 + 16 < K) {
#pragma unroll
            for (int i = 0; i < 8; i++)
                a8[i] = Ap[(size_t)(k0 + 16 + ak2*2 + i)*NN];
            b4 = *(const float4*)(Bp + k0 + 16);
        }
        uint32_t ahf[2][4], alf[2][4], bhf[4][2], blf[4][2];
#pragma unroll
        for (int mi = 0; mi < 2; mi++) {
            int mo = wm + mi*16 + gid;
            ahf[mi][0] = Ah[ tig   *SA + mo];
            ahf[mi][1] = Ah[ tig   *SA + mo + 8];
            ahf[mi][2] = Ah[(tig+4)*SA + mo];
            ahf[mi][3] = Ah[(tig+4)*SA + mo + 8];
            alf[mi][0] = Al[ tig   *SA + mo];
            alf[mi][1] = Al[ tig   *SA + mo + 8];
            alf[mi][2] = Al[(tig+4)*SA + mo];
            alf[mi][3] = Al[(tig+4)*SA + mo + 8];
        }
#pragma unroll
        for (int ni = 0; ni < 4; ni++) {
            int no = wn + ni*8 + gid;
            bhf[ni][0] = Bh[ tig   *SB + no];
            bhf[ni][1] = Bh[(tig+4)*SB + no];
            blf[ni][0] = Bl[ tig   *SB + no];
            blf[ni][1] = Bl[(tig+4)*SB + no];
        }
#pragma unroll
        for (int mi = 0; mi < 2; mi++)
#pragma unroll
            for (int ni = 0; ni < 4; ni++) {
                mma_bf16(acc[mi][ni], ahf[mi][0], ahf[mi][1], ahf[mi][2], ahf[mi][3],
                         bhf[ni][0], bhf[ni][1]);
                mma_bf16(acc[mi][ni], ahf[mi][0], ahf[mi][1], ahf[mi][2], ahf[mi][3],
                         blf[ni][0], blf[ni][1]);
                mma_bf16(acc[mi][ni], alf[mi][0], alf[mi][1], alf[mi][2], alf[mi][3],
                         bhf[ni][0], bhf[ni][1]);
            }
        __syncthreads();
    }
}

// ---------------------------------------------------------------------------
// tf32 single-pass GEMM core (gc, fc2), register-prefetch pipelined.
template<int K>
__device__ __forceinline__ void tf32_gemm_tile(
    const float* __restrict__ A, const float* __restrict__ B,
    uint32_t* Ask, uint32_t* Bsk, float acc[2][4][4], int tid)
{
    const int lane = tid & 31, w = tid >> 5;
    const int gid = lane >> 2, tig = lane & 3;
    const int wm = (w & 3) * 32, wn = (w >> 2) * 32;
    const int am = tid >> 1, ak = (tid & 1) * 8;
    const int bn = tid >> 2, bk = (tid & 3) * 4;

    const float* Ap = A + (size_t)am*K + ak;
    const float* Bp = B + (size_t)bn*K + bk;
    float4 a4a = *(const float4*)(Ap);
    float4 a4b = *(const float4*)(Ap + 4);
    float4 b4  = *(const float4*)(Bp);

    for (int k0 = 0; k0 < K; k0 += 16) {
        Ask[(ak+0)*SA + am] = f2tf32(a4a.x);
        Ask[(ak+1)*SA + am] = f2tf32(a4a.y);
        Ask[(ak+2)*SA + am] = f2tf32(a4a.z);
        Ask[(ak+3)*SA + am] = f2tf32(a4a.w);
        Ask[(ak+4)*SA + am] = f2tf32(a4b.x);
        Ask[(ak+5)*SA + am] = f2tf32(a4b.y);
        Ask[(ak+6)*SA + am] = f2tf32(a4b.z);
        Ask[(ak+7)*SA + am] = f2tf32(a4b.w);
        Bsk[(bk+0)*SB + bn] = f2tf32(b4.x);
        Bsk[(bk+1)*SB + bn] = f2tf32(b4.y);
        Bsk[(bk+2)*SB + bn] = f2tf32(b4.z);
        Bsk[(bk+3)*SB + bn] = f2tf32(b4.w);
        __syncthreads();
        if (k0 + 16 < K) {
            a4a = *(const float4*)(Ap + k0 + 16);
            a4b = *(const float4*)(Ap + k0 + 20);
            b4  = *(const float4*)(Bp + k0 + 16);
        }
#pragma unroll
        for (int ks = 0; ks < 16; ks += 8) {
            uint32_t af[2][4], bf[4][2];
#pragma unroll
            for (int mi = 0; mi < 2; mi++) {
                int mo = wm + mi*16 + gid;
                af[mi][0] = Ask[(ks+tig  )*SA + mo];
                af[mi][1] = Ask[(ks+tig  )*SA + mo + 8];
                af[mi][2] = Ask[(ks+tig+4)*SA + mo];
                af[mi][3] = Ask[(ks+tig+4)*SA + mo + 8];
            }
#pragma unroll
            for (int ni = 0; ni < 4; ni++) {
                int no = wn + ni*8 + gid;
                bf[ni][0] = Bsk[(ks+tig  )*SB + no];
                bf[ni][1] = Bsk[(ks+tig+4)*SB + no];
            }
#pragma unroll
            for (int mi = 0; mi < 2; mi++)
#pragma unroll
                for (int ni = 0; ni < 4; ni++)
                    mma_tf32(acc[mi][ni], af[mi][0], af[mi][1], af[mi][2], af[mi][3],
                             bf[ni][0], bf[ni][1]);
        }
        __syncthreads();
    }
}

// ---------------------------------------------------------------------------
// Kernel 1 (split-bf16): h = BN1(fc1_w @ xT + fc1_b), node-major output.
// Grid: (c-blocks fastest, r-blocks) for A-row L2 reuse.
__global__ void __launch_bounds__(256) fc1_kernel(
    const float* __restrict__ x,
    const float* __restrict__ w, const float* __restrict__ bias,
    const float* __restrict__ bg, const float* __restrict__ bbta,
    const float* __restrict__ bm, const float* __restrict__ bv)
{
    __shared__ __align__(16) char sbuf[BF_GEMM];
    uint32_t* Ah = (uint32_t*)sbuf;
    uint32_t* Al = (uint32_t*)(sbuf + BF_AH);
    uint32_t* Bh = (uint32_t*)(sbuf + BF_AB);
    uint32_t* Bl = (uint32_t*)(sbuf + BF_AB + BF_BH);
    const int r0 = blockIdx.y * 128;
    const int c0 = blockIdx.x * 64;
    const int tid = threadIdx.x;

    float acc[2][4][4];
#pragma unroll
    for (int mi = 0; mi < 2; mi++)
#pragma unroll
        for (int ni = 0; ni < 4; ni++)
#pragma unroll
            for (int q = 0; q < 4; q++) acc[mi][ni][q] = 0.f;

    bfs_gemm_fc1(x, r0, w + (size_t)c0*CC, Ah, Al, Bh, Bl, acc, tid);

    const int lane = tid & 31, wp = tid >> 5;
    const int gid = lane >> 2, tig = lane & 3;
    const int wm = (wp & 3) * 32, wn = (wp >> 2) * 32;
#pragma unroll
    for (int ni = 0; ni < 4; ni++) {
        int col = c0 + wn + ni*8 + 2*tig;
        float sca = bg[col]   * rsqrtf(bv[col]   + 1e-5f);
        float scb = bg[col+1] * rsqrtf(bv[col+1] + 1e-5f);
        float sha = bbta[col]   - bm[col]  *sca;
        float shb = bbta[col+1] - bm[col+1]*scb;
        float bia = bias[col], bib = bias[col+1];
#pragma unroll
        for (int mi = 0; mi < 2; mi++) {
            int r_lo = r0 + wm + mi*16 + gid;
#pragma unroll
            for (int h = 0; h < 2; h++) {
                int r = r_lo + h*8;
                float2 v2;
                v2.x = (acc[mi][ni][2*h]   + bia)*sca + sha;
                v2.y = (acc[mi][ni][2*h+1] + bib)*scb + shb;
                *(float2*)(g_h + (size_t)r*CC + col) = v2;
            }
        }
    }
}

// ---------------------------------------------------------------------------
// Kernel 2: row squared norms of h (MLP=8 batched loads, same fma order).
__global__ void x2_kernel()
{
    int warp = (blockIdx.x*blockDim.x + threadIdx.x) >> 5;
    int lane = threadIdx.x & 31;
    if (warp >= MTOT) return;
    const float* r = g_h + (size_t)warp*CC;
    float v[8];
#pragma unroll
    for (int i = 0; i < 8; i++) v[i] = r[lane + i*32];
    float s = 0.f;
#pragma unroll
    for (int i = 0; i < 8; i++) s = fmaf(v[i], v[i], s);
#pragma unroll
    for (int o = 16; o; o >>= 1) s += __shfl_xor_sync(0xffffffffu, s, o);
    if (!lane) g_x2[warp] = s;
}

// ---------------------------------------------------------------------------
// Kernel 3 (split-bf16, symmetric): dist[b][n][m] = x2[n]+x2[m]-2<h_n,h_m>.
// 128(n) x 64(m) tiles; compute only blocks with bj >= 2*bi; fill the rest
// via guarded transpose writes. GEMM smem aliased with transpose stage.
__global__ void __launch_bounds__(256) dist_kernel()
{
    __shared__ __align__(16) char sbuf[64*129*4];   // 33024 B, covers both uses
    uint32_t* Ah = (uint32_t*)sbuf;
    uint32_t* Al = (uint32_t*)(sbuf + BF_AH);
    uint32_t* Bh = (uint32_t*)(sbuf + BF_AB);
    uint32_t* Bl = (uint32_t*)(sbuf + BF_AB + BF_BH);
    float (*Os)[129] = (float(*)[129])sbuf;
    const int b = blockIdx.z;
    int t = blockIdx.x;
    int bi = 0;
    while (t >= 16 - 2*bi) { t -= 16 - 2*bi; bi++; }
    const int bj = 2*bi + t;
    const int n0 = bi * 128;
    const int m0 = bj * 64;
    const int tid = threadIdx.x;
    const float* hb = g_h + (size_t)b*NN*CC;

    float acc[2][4][4];
#pragma unroll
    for (int mi = 0; mi < 2; mi++)
#pragma unroll
        for (int ni = 0; ni < 4; ni++)
#pragma unroll
            for (int q = 0; q < 4; q++) acc[mi][ni][q] = 0.f;

    bfs_gemm_tile<CC>(hb + (size_t)n0*CC, hb + (size_t)m0*CC, Ah, Al, Bh, Bl, acc, tid);

    float* db = g_dist + (size_t)b*NN*NN;
    const int lane = tid & 31, wp = tid >> 5;
    const int gid = lane >> 2, tig = lane & 3;
    const int wm = (wp & 3) * 32, wn = (wp >> 2) * 32;
#pragma unroll
    for (int ni = 0; ni < 4; ni++) {
        int cl = wn + ni*8 + 2*tig;
        float xa = g_x2[b*NN + m0 + cl];
        float xb2 = g_x2[b*NN + m0 + cl + 1];
#pragma unroll
        for (int mi = 0; mi < 2; mi++) {
            int rl_lo = wm + mi*16 + gid;
#pragma unroll
            for (int h = 0; h < 2; h++) {
                int rl = rl_lo + h*8;
                int n = n0 + rl;
                float xn = g_x2[b*NN + n];
                float2 v2;
                v2.x = xn + xa  - 2.f*acc[mi][ni][2*h];
                v2.y = xn + xb2 - 2.f*acc[mi][ni][2*h+1];
                *(float2*)(db + (size_t)n*NN + m0 + cl) = v2;    // direct tile
                Os[cl][rl]   = v2.x;                              // transpose stage
                Os[cl+1][rl] = v2.y;
            }
        }
    }
    __syncthreads();
    // transpose write: dist[m][n], skip positions already direct-covered
#pragma unroll
    for (int it = 0; it < 32; it++) {
        int e = tid + it*256;     // 8192 elements
        int il = e & 127;         // local n (fastest -> coalesced)
        int jl = e >> 7;          // local m
        int r = m0 + jl;
        int c = n0 + il;
        if ((c >> 6) < 2*(r >> 7))
            db[(size_t)r*NN + c] = Os[jl][il];
    }
}

// ---------------------------------------------------------------------------
// Kernel 4: top-9 smallest per row (tie -> lower index). Warp per row,
// per-lane top-2 cache + lazy bitmask removal + REDUX reductions.
__global__ void __launch_bounds__(256) topk_kernel()
{
    const int w = threadIdx.x >> 5, lane = threadIdx.x & 31;
    const int row = blockIdx.x*8 + w;                // 8 warps/block
    const float* d = g_dist + (size_t)row * NN;

    unsigned u[32];
#pragma unroll
    for (int j = 0; j < 32; j++) {
        unsigned t = __float_as_uint(d[lane + j*32]);
        u[j] = (t & 0x80000000u) ? ~t : (t | 0x80000000u);   // monotonic map
    }

    unsigned m1 = u[0], m2 = 0xffffffffu;
    int i1 = 0, i2 = 0;
#pragma unroll
    for (int j = 1; j < 32; j++) {
        if (u[j] < m1)      { m2 = m1; i2 = i1; m1 = u[j]; i1 = j; }
        else if (u[j] < m2) { m2 = u[j]; i2 = j; }
    }
    bool have2 = true;
    unsigned removed = 0;

    for (int kp = 0; kp < KNN; kp++) {
        unsigned gm = __reduce_min_sync(0xffffffffu, m1);
        unsigned cand = (m1 == gm) ? (unsigned)(lane + (i1 << 5)) : 0xffffffffu;
        int sidx = (int)__reduce_min_sync(0xffffffffu, cand);
        if (!lane) g_idx[row*KNN + kp] = sidx;
        if ((sidx & 31) == lane) {
            removed |= 1u << i1;
            if (have2) { m1 = m2; i1 = i2; have2 = false; }
            else {
                m1 = 0xffffffffu; m2 = 0xffffffffu; i1 = 0; i2 = 0;
#pragma unroll
                for (int j = 0; j < 32; j++) {
                    unsigned uu = ((removed >> j) & 1u) ? 0xffffffffu : u[j];
                    if (uu < m1)      { m2 = m1; i2 = i1; m1 = uu; i1 = j; }
                    else if (uu < m2) { m2 = uu; i2 = j; }
                }
                have2 = true;
            }
        }
    }
}

// ---------------------------------------------------------------------------
// Kernel 5: MRConv + interleave (batched neighbor loads, same fmaxf order).
__global__ void mrconv_kernel()
{
    const int n = blockIdx.x, b = blockIdx.y, c = threadIdx.x;  // 256 threads
    const size_t rowb = (size_t)b*NN + n;
    __shared__ int sidx[KNN];
    if (c < KNN) sidx[c] = g_idx[rowb*KNN + c];
    __syncthreads();
    float v = g_h[rowb*CC + c];
    float nv[KNN];
#pragma unroll
    for (int j = 0; j < KNN; j++)
        nv[j] = g_h[((size_t)b*NN + sidx[j])*CC + c];
    float mx = -INFINITY;
#pragma unroll
    for (int j = 0; j < KNN; j++)
        mx = fmaxf(mx, nv[j] - v);
    float* mo = g_m + rowb*2*CC;
    mo[2*c]   = v;
    mo[2*c+1] = mx;
}

// ---------------------------------------------------------------------------
// Kernel 6 (tf32 mma): g = GELU(BN2(GBN(gc_w @ m + gc_b)))
// Grid: (c-blocks fastest, r-blocks) for A-row L2 reuse.
__global__ void __launch_bounds__(256) gc_kernel(
    const float* __restrict__ w, const float* __restrict__ bias,
    const float* __restrict__ g1g, const float* __restrict__ g1b,
    const float* __restrict__ g1m, const float* __restrict__ g1v,
    const float* __restrict__ g2g, const float* __restrict__ g2b,
    const float* __restrict__ g2m, const float* __restrict__ g2v)
{
    __shared__ __align__(16) char sbuf[TF_GEMM];
    uint32_t* Ask = (uint32_t*)sbuf;
    uint32_t* Bsk = (uint32_t*)(sbuf + TF_A);
    const int r0 = blockIdx.y * 128;
    const int c0 = blockIdx.x * 64;
    const int tid = threadIdx.x;

    float acc[2][4][4];
#pragma unroll
    for (int mi = 0; mi < 2; mi++)
#pragma unroll
        for (int ni = 0; ni < 4; ni++)
#pragma unroll
            for (int q = 0; q < 4; q++) acc[mi][ni][q] = 0.f;

    tf32_gemm_tile<2*CC>(g_m + (size_t)r0*(2*CC), w + (size_t)c0*(2*CC), Ask, Bsk, acc, tid);

    const int lane = tid & 31, wp = tid >> 5;
    const int gid = lane >> 2, tig = lane & 3;
    const int wm = (wp & 3) * 32, wn = (wp >> 2) * 32;
#pragma unroll
    for (int ni = 0; ni < 4; ni++) {
        int col = c0 + wn + ni*8 + 2*tig;
        float s1a = g1g[col]   * rsqrtf(g1v[col]   + 1e-5f);
        float s1b = g1g[col+1] * rsqrtf(g1v[col+1] + 1e-5f);
        float t1a = g1b[col]   - g1m[col]  *s1a;
        float t1b = g1b[col+1] - g1m[col+1]*s1b;
        float s2a = g2g[col]   * rsqrtf(g2v[col]   + 1e-5f);
        float s2b = g2g[col+1] * rsqrtf(g2v[col+1] + 1e-5f);
        float t2a = g2b[col]   - g2m[col]  *s2a;
        float t2b = g2b[col+1] - g2m[col+1]*s2b;
        float bia = bias[col], bib = bias[col+1];
#pragma unroll
        for (int mi = 0; mi < 2; mi++) {
            int r_lo = r0 + wm + mi*16 + gid;
#pragma unroll
            for (int h = 0; h < 2; h++) {
                int r = r_lo + h*8;
                float ya = ((acc[mi][ni][2*h]   + bia)*s1a + t1a)*s2a + t2a;
                float yb = ((acc[mi][ni][2*h+1] + bib)*s1b + t1b)*s2b + t2b;
                ya = 0.5f * ya * (1.f + erff(ya * 0.70710678118654752440f));
                yb = 0.5f * yb * (1.f + erff(yb * 0.70710678118654752440f));
                float2 v2; v2.x = ya; v2.y = yb;
                *(float2*)(g_g + (size_t)r*HID + col) = v2;
            }
        }
    }
}

// ---------------------------------------------------------------------------
// Kernel 7 (tf32 mma): out = BN3(fc2_w @ g + fc2_b) + x, (B,C,N) layout via
// smem restage (aliased with GEMM smem) for coalesced transposed stores.
// Grid: (c-blocks fastest, r-blocks) for A-row L2 reuse.
__global__ void __launch_bounds__(256) fc2_kernel(
    const float* __restrict__ w, const float* __restrict__ bias,
    const float* __restrict__ bg, const float* __restrict__ bbta,
    const float* __restrict__ bm, const float* __restrict__ bv,
    const float* __restrict__ x, float* __restrict__ out)
{
    __shared__ __align__(16) char sbuf[128*65*4];   // 33280 B, covers both uses
    uint32_t* Ask = (uint32_t*)sbuf;
    uint32_t* Bsk = (uint32_t*)(sbuf + TF_A);
    float* Os = (float*)sbuf;
    const int r0 = blockIdx.y * 128;
    const int c0 = blockIdx.x * 64;
    const int tid = threadIdx.x;

    float acc[2][4][4];
#pragma unroll
    for (int mi = 0; mi < 2; mi++)
#pragma unroll
        for (int ni = 0; ni < 4; ni++)
#pragma unroll
            for (int q = 0; q < 4; q++) acc[mi][ni][q] = 0.f;

    tf32_gemm_tile<HID>(g_g + (size_t)r0*HID, w + (size_t)c0*HID, Ask, Bsk, acc, tid);
    __syncthreads();   // GEMM smem dead; safe to reuse as Os

    const int lane = tid & 31, wp = tid >> 5;
    const int gid = lane >> 2, tig = lane & 3;
    const int wm = (wp & 3) * 32, wn = (wp >> 2) * 32;
#pragma unroll
    for (int ni = 0; ni < 4; ni++) {
        int cl = wn + ni*8 + 2*tig;
        int col = c0 + cl;
        float sca = bg[col]   * rsqrtf(bv[col]   + 1e-5f);
        float scb = bg[col+1] * rsqrtf(bv[col+1] + 1e-5f);
        float sha = bbta[col]   - bm[col]  *sca;
        float shb = bbta[col+1] - bm[col+1]*scb;
        float bia = bias[col], bib = bias[col+1];
#pragma unroll
        for (int mi = 0; mi < 2; mi++) {
            int rl_lo = wm + mi*16 + gid;
#pragma unroll
            for (int h = 0; h < 2; h++) {
                int rl = rl_lo + h*8;
                Os[rl*65 + cl]     = (acc[mi][ni][2*h]   + bia)*sca + sha;
                Os[rl*65 + cl + 1] = (acc[mi][ni][2*h+1] + bib)*scb + shb;
            }
        }
    }
    __syncthreads();
    const int b = r0 >> 10;
    const int nbase = r0 & 1023;
#pragma unroll
    for (int it = 0; it < 32; it++) {
        int e = tid + it*256;     // 8192 elements
        int nl = e & 127;
        int cl = e >> 7;
        size_t o = (size_t)b*CC*NN + (size_t)(c0 + cl)*NN + (nbase + nl);
        out[o] = Os[nl*65 + cl] + x[o];
    }
}

// ---------------------------------------------------------------------------
extern "C" void kernel_launch(void* const* d_in, const int* in_sizes, int n_in,
                              void* d_out, int out_size)
{
    const float* x     = (const float*)d_in[0];
    const float* fc1_w = (const float*)d_in[1];
    const float* fc1_b = (const float*)d_in[2];
    const float* bn1_g = (const float*)d_in[3];
    const float* bn1_b = (const float*)d_in[4];
    const float* bn1_m = (const float*)d_in[5];
    const float* bn1_v = (const float*)d_in[6];
    const float* gc_w  = (const float*)d_in[7];
    const float* gc_b  = (const float*)d_in[8];
    const float* gbn_g = (const float*)d_in[9];
    const float* gbn_b = (const float*)d_in[10];
    const float* gbn_m = (const float*)d_in[11];
    const float* gbn_v = (const float*)d_in[12];
    const float* bn2_g = (const float*)d_in[13];
    const float* bn2_b = (const float*)d_in[14];
    const float* bn2_m = (const float*)d_in[15];
    const float* bn2_v = (const float*)d_in[16];
    const float* fc2_w = (const float*)d_in[17];
    const float* fc2_b = (const float*)d_in[18];
    const float* bn3_g = (const float*)d_in[19];
    const float* bn3_b = (const float*)d_in[20];
    const float* bn3_m = (const float*)d_in[21];
    const float* bn3_v = (const float*)d_in[22];
    float* out = (float*)d_out;

    // 1) fc1 + BN1 -> h (split-bf16 tensor cores, c-fastest grid)
    {
        dim3 grid(CC/64, MTOT/128);
        fc1_kernel<<<grid, 256>>>(x, fc1_w, fc1_b, bn1_g, bn1_b, bn1_m, bn1_v);
    }
    // 2) row norms
    x2_kernel<<<(MTOT*32)/256, 256>>>();
    // 3) pairwise distances (split-bf16, symmetric triangular blocks)
    {
        dim3 grid(72, 1, BB);
        dist_kernel<<<grid, 256>>>();
    }
    // 4) top-9 nearest per node (warp per row, top-2 cache + REDUX)
    topk_kernel<<<MTOT/8, 256>>>();
    // 5) MRConv + interleave
    {
        dim3 grid(NN, BB);
        mrconv_kernel<<<grid, 256>>>();
    }
    // 6) gc + gbn + bn2 + GELU (tf32 tensor cores, c-fastest grid)
    {
        dim3 grid(HID/64, MTOT/128);
        gc_kernel<<<grid, 256>>>(gc_w, gc_b, gbn_g, gbn_b, gbn_m, gbn_v,
                                 bn2_g, bn2_b, bn2_m, bn2_v);
    }
    // 7) fc2 + bn3 + residual (tf32 tensor cores, c-fastest grid)
    {
        dim3 grid(CC/64, MTOT/128);
        fc2_kernel<<<grid, 256>>>(fc2_w, fc2_b, bn3_g, bn3_b, bn3_m, bn3_v, x, out);
    }
}

// round 16
// speedup vs baseline: 1.0479x; 1.0215x over previous
#include <cuda_runtime.h>
#include <cuda_bf16.h>
#include <stdint.h>
#include <math.h>

// Problem constants
#define BB   16
#define CC   256
#define NN   1024
#define HID  512
#define KNN  9
#define MTOT (BB*NN)   // 16384

// smem strides (u32 words), % 32 == 8 -> conflict-free fragment LDS
#define SA 136
#define SB 72

// GEMM smem sub-buffer sizes (bytes)
#define BF_AH (8*SA*4)      // 4352
#define BF_AB (2*BF_AH)     // Ah+Al
#define BF_BH (8*SB*4)      // 2304
#define BF_GEMM (BF_AB + 2*BF_BH)          // 13312  (split-bf16 core)
#define TF_A (16*SA*4)      // 8704
#define TF_B (16*SB*4)      // 4608
#define TF_GEMM (TF_A + TF_B)              // 13312  (tf32 core)

// ---------------- scratch (static device globals; no allocations) ----------
__device__ float g_h   [(size_t)MTOT*CC];       // node-major h
__device__ float g_x2  [MTOT];                  // row squared norms
__device__ float g_dist[(size_t)BB*NN*NN];      // per-batch distance matrices
__device__ int   g_idx [MTOT*KNN];              // knn indices (batch-local)
__device__ float g_m   [(size_t)MTOT*2*CC];     // interleaved [h, maxdiff]
__device__ float g_g   [(size_t)MTOT*HID];      // post-GELU activations

// ---------------------------------------------------------------------------
// mma helpers
__device__ __forceinline__ uint32_t f2tf32(float f){
    uint32_t u; asm("cvt.rna.tf32.f32 %0, %1;" : "=r"(u) : "f"(f)); return u;
}
__device__ __forceinline__ void mma_tf32(float* c,
    uint32_t a0, uint32_t a1, uint32_t a2, uint32_t a3, uint32_t b0, uint32_t b1)
{
    asm volatile("mma.sync.aligned.m16n8k8.row.col.f32.tf32.tf32.f32 "
        "{%0,%1,%2,%3}, {%4,%5,%6,%7}, {%8,%9}, {%0,%1,%2,%3};"
        : "+f"(c[0]), "+f"(c[1]), "+f"(c[2]), "+f"(c[3])
        : "r"(a0), "r"(a1), "r"(a2), "r"(a3), "r"(b0), "r"(b1));
}
__device__ __forceinline__ void mma_bf16(float* c,
    uint32_t a0, uint32_t a1, uint32_t a2, uint32_t a3, uint32_t b0, uint32_t b1)
{
    asm volatile("mma.sync.aligned.m16n8k16.row.col.f32.bf16.bf16.f32 "
        "{%0,%1,%2,%3}, {%4,%5,%6,%7}, {%8,%9}, {%0,%1,%2,%3};"
        : "+f"(c[0]), "+f"(c[1]), "+f"(c[2]), "+f"(c[3])
        : "r"(a0), "r"(a1), "r"(a2), "r"(a3), "r"(b0), "r"(b1));
}

// split two floats (consecutive k) into packed bf16x2 hi and lo words
__device__ __forceinline__ void splitpack(float x, float y, uint32_t& h, uint32_t& l){
    __nv_bfloat16 hx = __float2bfloat16(x);
    __nv_bfloat16 hy = __float2bfloat16(y);
    float rx = x - __bfloat162float(hx);
    float ry = y - __bfloat162float(hy);
    __nv_bfloat16 lx = __float2bfloat16(rx);
    __nv_bfloat16 ly = __float2bfloat16(ry);
    uint16_t hxb = *(uint16_t*)&hx, hyb = *(uint16_t*)&hy;
    uint16_t lxb = *(uint16_t*)&lx, lyb = *(uint16_t*)&ly;
    h = ((uint32_t)hyb << 16) | hxb;
    l = ((uint32_t)lyb << 16) | lxb;
}

// ---------------------------------------------------------------------------
// Split-bf16 (hi+lo, 3-pass) GEMM core, register-prefetch pipelined.
// Block tile 128x64, 256 threads, 8 warps x (32x32). A/B row-major float.
template<int K>
__device__ __forceinline__ void bfs_gemm_tile(
    const float* __restrict__ A, const float* __restrict__ B,
    uint32_t* Ah, uint32_t* Al, uint32_t* Bh, uint32_t* Bl,
    float acc[2][4][4], int tid)
{
    const int lane = tid & 31, w = tid >> 5;
    const int gid = lane >> 2, tig = lane & 3;
    const int wm = (w & 3) * 32, wn = (w >> 2) * 32;
    const int am = tid >> 1, ak2 = (tid & 1) * 4;  // A: 128 rows, 2 thr/row
    const int bn = tid >> 2, bk2 = (tid & 3) * 2;  // B: 64 rows, 4 thr/row

    const float* Ap = A + (size_t)am*K + ak2*2;
    const float* Bp = B + (size_t)bn*K + bk2*2;
    float4 a4a = *(const float4*)(Ap);
    float4 a4b = *(const float4*)(Ap + 4);
    float4 b4  = *(const float4*)(Bp);

    for (int k0 = 0; k0 < K; k0 += 16) {
        uint32_t h0,l0,h1,l1,h2,l2,h3,l3;
        splitpack(a4a.x, a4a.y, h0, l0);
        splitpack(a4a.z, a4a.w, h1, l1);
        splitpack(a4b.x, a4b.y, h2, l2);
        splitpack(a4b.z, a4b.w, h3, l3);
        Ah[(ak2+0)*SA + am] = h0; Al[(ak2+0)*SA + am] = l0;
        Ah[(ak2+1)*SA + am] = h1; Al[(ak2+1)*SA + am] = l1;
        Ah[(ak2+2)*SA + am] = h2; Al[(ak2+2)*SA + am] = l2;
        Ah[(ak2+3)*SA + am] = h3; Al[(ak2+3)*SA + am] = l3;
        uint32_t bh0,bl0,bh1,bl1;
        splitpack(b4.x, b4.y, bh0, bl0);
        splitpack(b4.z, b4.w, bh1, bl1);
        Bh[(bk2+0)*SB + bn] = bh0; Bl[(bk2+0)*SB + bn] = bl0;
        Bh[(bk2+1)*SB + bn] = bh1; Bl[(bk2+1)*SB + bn] = bl1;
        __syncthreads();
        if (k0 + 16 < K) {                       // prefetch next slab
            a4a = *(const float4*)(Ap + k0 + 16);
            a4b = *(const float4*)(Ap + k0 + 20);
            b4  = *(const float4*)(Bp + k0 + 16);
        }
        uint32_t ahf[2][4], alf[2][4], bhf[4][2], blf[4][2];
#pragma unroll
        for (int mi = 0; mi < 2; mi++) {
            int mo = wm + mi*16 + gid;
            ahf[mi][0] = Ah[ tig   *SA + mo];
            ahf[mi][1] = Ah[ tig   *SA + mo + 8];
            ahf[mi][2] = Ah[(tig+4)*SA + mo];
            ahf[mi][3] = Ah[(tig+4)*SA + mo + 8];
            alf[mi][0] = Al[ tig   *SA + mo];
            alf[mi][1] = Al[ tig   *SA + mo + 8];
            alf[mi][2] = Al[(tig+4)*SA + mo];
            alf[mi][3] = Al[(tig+4)*SA + mo + 8];
        }
#pragma unroll
        for (int ni = 0; ni < 4; ni++) {
            int no = wn + ni*8 + gid;
            bhf[ni][0] = Bh[ tig   *SB + no];
            bhf[ni][1] = Bh[(tig+4)*SB + no];
            blf[ni][0] = Bl[ tig   *SB + no];
            blf[ni][1] = Bl[(tig+4)*SB + no];
        }
#pragma unroll
        for (int mi = 0; mi < 2; mi++)
#pragma unroll
            for (int ni = 0; ni < 4; ni++) {
                mma_bf16(acc[mi][ni], ahf[mi][0], ahf[mi][1], ahf[mi][2], ahf[mi][3],
                         bhf[ni][0], bhf[ni][1]);
                mma_bf16(acc[mi][ni], ahf[mi][0], ahf[mi][1], ahf[mi][2], ahf[mi][3],
                         blf[ni][0], blf[ni][1]);
                mma_bf16(acc[mi][ni], alf[mi][0], alf[mi][1], alf[mi][2], alf[mi][3],
                         bhf[ni][0], bhf[ni][1]);
            }
        __syncthreads();
    }
}

// ---------------------------------------------------------------------------
// fc1 variant: A is read DIRECTLY from x (B,C,N) with transposed addressing.
__device__ __forceinline__ void bfs_gemm_fc1(
    const float* __restrict__ x, int r0,
    const float* __restrict__ B,
    uint32_t* Ah, uint32_t* Al, uint32_t* Bh, uint32_t* Bl,
    float acc[2][4][4], int tid)
{
    const int K = CC;
    const int lane = tid & 31, w = tid >> 5;
    const int gid = lane >> 2, tig = lane & 3;
    const int wm = (w & 3) * 32, wn = (w >> 2) * 32;
    const int am = tid >> 1, ak2 = (tid & 1) * 4;
    const int bn = tid >> 2, bk2 = (tid & 3) * 2;

    const int bb = r0 >> 10, n0l = r0 & 1023;
    const float* Ap = x + (size_t)bb*CC*NN + n0l + am;
    const float* Bp = B + (size_t)bn*K + bk2*2;

    float a8[8];
#pragma unroll
    for (int i = 0; i < 8; i++) a8[i] = Ap[(size_t)(ak2*2 + i)*NN];
    float4 b4 = *(const float4*)(Bp);

    for (int k0 = 0; k0 < K; k0 += 16) {
        uint32_t h0,l0,h1,l1,h2,l2,h3,l3;
        splitpack(a8[0], a8[1], h0, l0);
        splitpack(a8[2], a8[3], h1, l1);
        splitpack(a8[4], a8[5], h2, l2);
        splitpack(a8[6], a8[7], h3, l3);
        Ah[(ak2+0)*SA + am] = h0; Al[(ak2+0)*SA + am] = l0;
        Ah[(ak2+1)*SA + am] = h1; Al[(ak2+1)*SA + am] = l1;
        Ah[(ak2+2)*SA + am] = h2; Al[(ak2+2)*SA + am] = l2;
        Ah[(ak2+3)*SA + am] = h3; Al[(ak2+3)*SA + am] = l3;
        uint32_t bh0,bl0,bh1,bl1;
        splitpack(b4.x, b4.y, bh0, bl0);
        splitpack(b4.z, b4.w, bh1, bl1);
        Bh[(bk2+0)*SB + bn] = bh0; Bl[(bk2+0)*SB + bn] = bl0;
        Bh[(bk2+1)*SB + bn] = bh1; Bl[(bk2+1)*SB + bn] = bl1;
        __syncthreads();
        if (k0 + 16 < K) {
#pragma unroll
            for (int i = 0; i < 8; i++)
                a8[i] = Ap[(size_t)(k0 + 16 + ak2*2 + i)*NN];
            b4 = *(const float4*)(Bp + k0 + 16);
        }
        uint32_t ahf[2][4], alf[2][4], bhf[4][2], blf[4][2];
#pragma unroll
        for (int mi = 0; mi < 2; mi++) {
            int mo = wm + mi*16 + gid;
            ahf[mi][0] = Ah[ tig   *SA + mo];
            ahf[mi][1] = Ah[ tig   *SA + mo + 8];
            ahf[mi][2] = Ah[(tig+4)*SA + mo];
            ahf[mi][3] = Ah[(tig+4)*SA + mo + 8];
            alf[mi][0] = Al[ tig   *SA + mo];
            alf[mi][1] = Al[ tig   *SA + mo + 8];
            alf[mi][2] = Al[(tig+4)*SA + mo];
            alf[mi][3] = Al[(tig+4)*SA + mo + 8];
        }
#pragma unroll
        for (int ni = 0; ni < 4; ni++) {
            int no = wn + ni*8 + gid;
            bhf[ni][0] = Bh[ tig   *SB + no];
            bhf[ni][1] = Bh[(tig+4)*SB + no];
            blf[ni][0] = Bl[ tig   *SB + no];
            blf[ni][1] = Bl[(tig+4)*SB + no];
        }
#pragma unroll
        for (int mi = 0; mi < 2; mi++)
#pragma unroll
            for (int ni = 0; ni < 4; ni++) {
                mma_bf16(acc[mi][ni], ahf[mi][0], ahf[mi][1], ahf[mi][2], ahf[mi][3],
                         bhf[ni][0], bhf[ni][1]);
                mma_bf16(acc[mi][ni], ahf[mi][0], ahf[mi][1], ahf[mi][2], ahf[mi][3],
                         blf[ni][0], blf[ni][1]);
                mma_bf16(acc[mi][ni], alf[mi][0], alf[mi][1], alf[mi][2], alf[mi][3],
                         bhf[ni][0], bhf[ni][1]);
            }
        __syncthreads();
    }
}

// ---------------------------------------------------------------------------
// tf32 single-pass GEMM core (gc, fc2), register-prefetch pipelined.
template<int K>
__device__ __forceinline__ void tf32_gemm_tile(
    const float* __restrict__ A, const float* __restrict__ B,
    uint32_t* Ask, uint32_t* Bsk, float acc[2][4][4], int tid)
{
    const int lane = tid & 31, w = tid >> 5;
    const int gid = lane >> 2, tig = lane & 3;
    const int wm = (w & 3) * 32, wn = (w >> 2) * 32;
    const int am = tid >> 1, ak = (tid & 1) * 8;
    const int bn = tid >> 2, bk = (tid & 3) * 4;

    const float* Ap = A + (size_t)am*K + ak;
    const float* Bp = B + (size_t)bn*K + bk;
    float4 a4a = *(const float4*)(Ap);
    float4 a4b = *(const float4*)(Ap + 4);
    float4 b4  = *(const float4*)(Bp);

    for (int k0 = 0; k0 < K; k0 += 16) {
        Ask[(ak+0)*SA + am] = f2tf32(a4a.x);
        Ask[(ak+1)*SA + am] = f2tf32(a4a.y);
        Ask[(ak+2)*SA + am] = f2tf32(a4a.z);
        Ask[(ak+3)*SA + am] = f2tf32(a4a.w);
        Ask[(ak+4)*SA + am] = f2tf32(a4b.x);
        Ask[(ak+5)*SA + am] = f2tf32(a4b.y);
        Ask[(ak+6)*SA + am] = f2tf32(a4b.z);
        Ask[(ak+7)*SA + am] = f2tf32(a4b.w);
        Bsk[(bk+0)*SB + bn] = f2tf32(b4.x);
        Bsk[(bk+1)*SB + bn] = f2tf32(b4.y);
        Bsk[(bk+2)*SB + bn] = f2tf32(b4.z);
        Bsk[(bk+3)*SB + bn] = f2tf32(b4.w);
        __syncthreads();
        if (k0 + 16 < K) {
            a4a = *(const float4*)(Ap + k0 + 16);
            a4b = *(const float4*)(Ap + k0 + 20);
            b4  = *(const float4*)(Bp + k0 + 16);
        }
#pragma unroll
        for (int ks = 0; ks < 16; ks += 8) {
            uint32_t af[2][4], bf[4][2];
#pragma unroll
            for (int mi = 0; mi < 2; mi++) {
                int mo = wm + mi*16 + gid;
                af[mi][0] = Ask[(ks+tig  )*SA + mo];
                af[mi][1] = Ask[(ks+tig  )*SA + mo + 8];
                af[mi][2] = Ask[(ks+tig+4)*SA + mo];
                af[mi][3] = Ask[(ks+tig+4)*SA + mo + 8];
            }
#pragma unroll
            for (int ni = 0; ni < 4; ni++) {
                int no = wn + ni*8 + gid;
                bf[ni][0] = Bsk[(ks+tig  )*SB + no];
                bf[ni][1] = Bsk[(ks+tig+4)*SB + no];
            }
#pragma unroll
            for (int mi = 0; mi < 2; mi++)
#pragma unroll
                for (int ni = 0; ni < 4; ni++)
                    mma_tf32(acc[mi][ni], af[mi][0], af[mi][1], af[mi][2], af[mi][3],
                             bf[ni][0], bf[ni][1]);
        }
        __syncthreads();
    }
}

// ---------------------------------------------------------------------------
// Kernel 1 (split-bf16): h = BN1(fc1_w @ xT + fc1_b), node-major output.
__global__ void __launch_bounds__(256) fc1_kernel(
    const float* __restrict__ x,
    const float* __restrict__ w, const float* __restrict__ bias,
    const float* __restrict__ bg, const float* __restrict__ bbta,
    const float* __restrict__ bm, const float* __restrict__ bv)
{
    __shared__ __align__(16) char sbuf[BF_GEMM];
    uint32_t* Ah = (uint32_t*)sbuf;
    uint32_t* Al = (uint32_t*)(sbuf + BF_AH);
    uint32_t* Bh = (uint32_t*)(sbuf + BF_AB);
    uint32_t* Bl = (uint32_t*)(sbuf + BF_AB + BF_BH);
    const int r0 = blockIdx.y * 128;
    const int c0 = blockIdx.x * 64;
    const int tid = threadIdx.x;

    float acc[2][4][4];
#pragma unroll
    for (int mi = 0; mi < 2; mi++)
#pragma unroll
        for (int ni = 0; ni < 4; ni++)
#pragma unroll
            for (int q = 0; q < 4; q++) acc[mi][ni][q] = 0.f;

    bfs_gemm_fc1(x, r0, w + (size_t)c0*CC, Ah, Al, Bh, Bl, acc, tid);

    const int lane = tid & 31, wp = tid >> 5;
    const int gid = lane >> 2, tig = lane & 3;
    const int wm = (wp & 3) * 32, wn = (wp >> 2) * 32;
#pragma unroll
    for (int ni = 0; ni < 4; ni++) {
        int col = c0 + wn + ni*8 + 2*tig;
        float sca = bg[col]   * rsqrtf(bv[col]   + 1e-5f);
        float scb = bg[col+1] * rsqrtf(bv[col+1] + 1e-5f);
        float sha = bbta[col]   - bm[col]  *sca;
        float shb = bbta[col+1] - bm[col+1]*scb;
        float bia = bias[col], bib = bias[col+1];
#pragma unroll
        for (int mi = 0; mi < 2; mi++) {
            int r_lo = r0 + wm + mi*16 + gid;
#pragma unroll
            for (int h = 0; h < 2; h++) {
                int r = r_lo + h*8;
                float2 v2;
                v2.x = (acc[mi][ni][2*h]   + bia)*sca + sha;
                v2.y = (acc[mi][ni][2*h+1] + bib)*scb + shb;
                *(float2*)(g_h + (size_t)r*CC + col) = v2;
            }
        }
    }
}

// ---------------------------------------------------------------------------
// Kernel 2: row squared norms of h (MLP=8 batched loads, same fma order).
__global__ void x2_kernel()
{
    int warp = (blockIdx.x*blockDim.x + threadIdx.x) >> 5;
    int lane = threadIdx.x & 31;
    if (warp >= MTOT) return;
    const float* r = g_h + (size_t)warp*CC;
    float v[8];
#pragma unroll
    for (int i = 0; i < 8; i++) v[i] = r[lane + i*32];
    float s = 0.f;
#pragma unroll
    for (int i = 0; i < 8; i++) s = fmaf(v[i], v[i], s);
#pragma unroll
    for (int o = 16; o; o >>= 1) s += __shfl_xor_sync(0xffffffffu, s, o);
    if (!lane) g_x2[warp] = s;
}

// ---------------------------------------------------------------------------
// Kernel 3 (split-bf16, symmetric): dist[b][n][m] = x2[n]+x2[m]-2<h_n,h_m>.
// 128(n) x 64(m) tiles; compute only blocks with bj >= 2*bi; fill the rest
// via guarded transpose writes. GEMM smem aliased with transpose stage.
__global__ void __launch_bounds__(256) dist_kernel()
{
    __shared__ __align__(16) char sbuf[64*129*4];   // 33024 B, covers both uses
    uint32_t* Ah = (uint32_t*)sbuf;
    uint32_t* Al = (uint32_t*)(sbuf + BF_AH);
    uint32_t* Bh = (uint32_t*)(sbuf + BF_AB);
    uint32_t* Bl = (uint32_t*)(sbuf + BF_AB + BF_BH);
    float (*Os)[129] = (float(*)[129])sbuf;
    const int b = blockIdx.z;
    int t = blockIdx.x;
    int bi = 0;
    while (t >= 16 - 2*bi) { t -= 16 - 2*bi; bi++; }
    const int bj = 2*bi + t;
    const int n0 = bi * 128;
    const int m0 = bj * 64;
    const int tid = threadIdx.x;
    const float* hb = g_h + (size_t)b*NN*CC;

    float acc[2][4][4];
#pragma unroll
    for (int mi = 0; mi < 2; mi++)
#pragma unroll
        for (int ni = 0; ni < 4; ni++)
#pragma unroll
            for (int q = 0; q < 4; q++) acc[mi][ni][q] = 0.f;

    bfs_gemm_tile<CC>(hb + (size_t)n0*CC, hb + (size_t)m0*CC, Ah, Al, Bh, Bl, acc, tid);

    float* db = g_dist + (size_t)b*NN*NN;
    const int lane = tid & 31, wp = tid >> 5;
    const int gid = lane >> 2, tig = lane & 3;
    const int wm = (wp & 3) * 32, wn = (wp >> 2) * 32;
#pragma unroll
    for (int ni = 0; ni < 4; ni++) {
        int cl = wn + ni*8 + 2*tig;
        float xa = g_x2[b*NN + m0 + cl];
        float xb2 = g_x2[b*NN + m0 + cl + 1];
#pragma unroll
        for (int mi = 0; mi < 2; mi++) {
            int rl_lo = wm + mi*16 + gid;
#pragma unroll
            for (int h = 0; h < 2; h++) {
                int rl = rl_lo + h*8;
                int n = n0 + rl;
                float xn = g_x2[b*NN + n];
                float2 v2;
                v2.x = xn + xa  - 2.f*acc[mi][ni][2*h];
                v2.y = xn + xb2 - 2.f*acc[mi][ni][2*h+1];
                *(float2*)(db + (size_t)n*NN + m0 + cl) = v2;    // direct tile
                Os[cl][rl]   = v2.x;                              // transpose stage
                Os[cl+1][rl] = v2.y;
            }
        }
    }
    __syncthreads();
    // transpose write: dist[m][n], skip positions already direct-covered
#pragma unroll
    for (int it = 0; it < 32; it++) {
        int e = tid + it*256;     // 8192 elements
        int il = e & 127;         // local n (fastest -> coalesced)
        int jl = e >> 7;          // local m
        int r = m0 + jl;
        int c = n0 + il;
        if ((c >> 6) < 2*(r >> 7))
            db[(size_t)r*NN + c] = Os[jl][il];
    }
}

// ---------------------------------------------------------------------------
// Kernel 4: top-9 smallest per row (tie -> lower index). Warp per row,
// per-lane top-2 cache + lazy bitmask removal + REDUX reductions.
__global__ void __launch_bounds__(256) topk_kernel()
{
    const int w = threadIdx.x >> 5, lane = threadIdx.x & 31;
    const int row = blockIdx.x*8 + w;                // 8 warps/block
    const float* d = g_dist + (size_t)row * NN;

    unsigned u[32];
#pragma unroll
    for (int j = 0; j < 32; j++) {
        unsigned t = __float_as_uint(d[lane + j*32]);
        u[j] = (t & 0x80000000u) ? ~t : (t | 0x80000000u);   // monotonic map
    }

    unsigned m1 = u[0], m2 = 0xffffffffu;
    int i1 = 0, i2 = 0;
#pragma unroll
    for (int j = 1; j < 32; j++) {
        if (u[j] < m1)      { m2 = m1; i2 = i1; m1 = u[j]; i1 = j; }
        else if (u[j] < m2) { m2 = u[j]; i2 = j; }
    }
    bool have2 = true;
    unsigned removed = 0;

    for (int kp = 0; kp < KNN; kp++) {
        unsigned gm = __reduce_min_sync(0xffffffffu, m1);
        unsigned cand = (m1 == gm) ? (unsigned)(lane + (i1 << 5)) : 0xffffffffu;
        int sidx = (int)__reduce_min_sync(0xffffffffu, cand);
        if (!lane) g_idx[row*KNN + kp] = sidx;
        if ((sidx & 31) == lane) {
            removed |= 1u << i1;
            if (have2) { m1 = m2; i1 = i2; have2 = false; }
            else {
                m1 = 0xffffffffu; m2 = 0xffffffffu; i1 = 0; i2 = 0;
#pragma unroll
                for (int j = 0; j < 32; j++) {
                    unsigned uu = ((removed >> j) & 1u) ? 0xffffffffu : u[j];
                    if (uu < m1)      { m2 = m1; i2 = i1; m1 = uu; i1 = j; }
                    else if (uu < m2) { m2 = uu; i2 = j; }
                }
                have2 = true;
            }
        }
    }
}

// ---------------------------------------------------------------------------
// Kernel 5: MRConv + interleave, float4-vectorized (4 channels/thread,
// 4 nodes/block). Per-element fmaxf order identical -> bit-identical g_m.
__global__ void __launch_bounds__(256) mrconv_kernel()
{
    const int nl = threadIdx.x >> 6;         // node within block (0..3)
    const int tq = threadIdx.x & 63;         // channel quad (c = tq*4)
    const int n  = blockIdx.x*4 + nl;
    const int b  = blockIdx.y;
    const size_t rowb = (size_t)b*NN + n;

    __shared__ int sidx[4][KNN];
    if (threadIdx.x < 4*KNN) {
        int q = threadIdx.x / KNN, j = threadIdx.x % KNN;
        sidx[q][j] = g_idx[((size_t)b*NN + blockIdx.x*4 + q)*KNN + j];
    }
    __syncthreads();

    const int c = tq*4;
    float4 v = *(const float4*)(g_h + rowb*CC + c);
    float4 nv[KNN];
#pragma unroll
    for (int j = 0; j < KNN; j++)
        nv[j] = *(const float4*)(g_h + ((size_t)b*NN + sidx[nl][j])*CC + c);
    float4 mx = make_float4(-INFINITY, -INFINITY, -INFINITY, -INFINITY);
#pragma unroll
    for (int j = 0; j < KNN; j++) {
        mx.x = fmaxf(mx.x, nv[j].x - v.x);
        mx.y = fmaxf(mx.y, nv[j].y - v.y);
        mx.z = fmaxf(mx.z, nv[j].z - v.z);
        mx.w = fmaxf(mx.w, nv[j].w - v.w);
    }
    float* mo = g_m + rowb*2*CC + 2*c;
    float4 o0 = make_float4(v.x, mx.x, v.y, mx.y);
    float4 o1 = make_float4(v.z, mx.z, v.w, mx.w);
    *(float4*)(mo)     = o0;
    *(float4*)(mo + 4) = o1;
}

// ---------------------------------------------------------------------------
// Kernel 6 (tf32 mma): g = GELU(BN2(GBN(gc_w @ m + gc_b)))
__global__ void __launch_bounds__(256) gc_kernel(
    const float* __restrict__ w, const float* __restrict__ bias,
    const float* __restrict__ g1g, const float* __restrict__ g1b,
    const float* __restrict__ g1m, const float* __restrict__ g1v,
    const float* __restrict__ g2g, const float* __restrict__ g2b,
    const float* __restrict__ g2m, const float* __restrict__ g2v)
{
    __shared__ __align__(16) char sbuf[TF_GEMM];
    uint32_t* Ask = (uint32_t*)sbuf;
    uint32_t* Bsk = (uint32_t*)(sbuf + TF_A);
    const int r0 = blockIdx.y * 128;
    const int c0 = blockIdx.x * 64;
    const int tid = threadIdx.x;

    float acc[2][4][4];
#pragma unroll
    for (int mi = 0; mi < 2; mi++)
#pragma unroll
        for (int ni = 0; ni < 4; ni++)
#pragma unroll
            for (int q = 0; q < 4; q++) acc[mi][ni][q] = 0.f;

    tf32_gemm_tile<2*CC>(g_m + (size_t)r0*(2*CC), w + (size_t)c0*(2*CC), Ask, Bsk, acc, tid);

    const int lane = tid & 31, wp = tid >> 5;
    const int gid = lane >> 2, tig = lane & 3;
    const int wm = (wp & 3) * 32, wn = (wp >> 2) * 32;
#pragma unroll
    for (int ni = 0; ni < 4; ni++) {
        int col = c0 + wn + ni*8 + 2*tig;
        float s1a = g1g[col]   * rsqrtf(g1v[col]   + 1e-5f);
        float s1b = g1g[col+1] * rsqrtf(g1v[col+1] + 1e-5f);
        float t1a = g1b[col]   - g1m[col]  *s1a;
        float t1b = g1b[col+1] - g1m[col+1]*s1b;
        float s2a = g2g[col]   * rsqrtf(g2v[col]   + 1e-5f);
        float s2b = g2g[col+1] * rsqrtf(g2v[col+1] + 1e-5f);
        float t2a = g2b[col]   - g2m[col]  *s2a;
        float t2b = g2b[col+1] - g2m[col+1]*s2b;
        float bia = bias[col], bib = bias[col+1];
#pragma unroll
        for (int mi = 0; mi < 2; mi++) {
            int r_lo = r0 + wm + mi*16 + gid;
#pragma unroll
            for (int h = 0; h < 2; h++) {
                int r = r_lo + h*8;
                float ya = ((acc[mi][ni][2*h]   + bia)*s1a + t1a)*s2a + t2a;
                float yb = ((acc[mi][ni][2*h+1] + bib)*s1b + t1b)*s2b + t2b;
                ya = 0.5f * ya * (1.f + erff(ya * 0.70710678118654752440f));
                yb = 0.5f * yb * (1.f + erff(yb * 0.70710678118654752440f));
                float2 v2; v2.x = ya; v2.y = yb;
                *(float2*)(g_g + (size_t)r*HID + col) = v2;
            }
        }
    }
}

// ---------------------------------------------------------------------------
// Kernel 7 (tf32 mma): out = BN3(fc2_w @ g + fc2_b) + x, (B,C,N) layout via
// smem restage (aliased with GEMM smem) for coalesced transposed stores.
__global__ void __launch_bounds__(256) fc2_kernel(
    const float* __restrict__ w, const float* __restrict__ bias,
    const float* __restrict__ bg, const float* __restrict__ bbta,
    const float* __restrict__ bm, const float* __restrict__ bv,
    const float* __restrict__ x, float* __restrict__ out)
{
    __shared__ __align__(16) char sbuf[128*65*4];   // 33280 B, covers both uses
    uint32_t* Ask = (uint32_t*)sbuf;
    uint32_t* Bsk = (uint32_t*)(sbuf + TF_A);
    float* Os = (float*)sbuf;
    const int r0 = blockIdx.y * 128;
    const int c0 = blockIdx.x * 64;
    const int tid = threadIdx.x;

    float acc[2][4][4];
#pragma unroll
    for (int mi = 0; mi < 2; mi++)
#pragma unroll
        for (int ni = 0; ni < 4; ni++)
#pragma unroll
            for (int q = 0; q < 4; q++) acc[mi][ni][q] = 0.f;

    tf32_gemm_tile<HID>(g_g + (size_t)r0*HID, w + (size_t)c0*HID, Ask, Bsk, acc, tid);
    __syncthreads();   // GEMM smem dead; safe to reuse as Os

    const int lane = tid & 31, wp = tid >> 5;
    const int gid = lane >> 2, tig = lane & 3;
    const int wm = (wp & 3) * 32, wn = (wp >> 2) * 32;
#pragma unroll
    for (int ni = 0; ni < 4; ni++) {
        int cl = wn + ni*8 + 2*tig;
        int col = c0 + cl;
        float sca = bg[col]   * rsqrtf(bv[col]   + 1e-5f);
        float scb = bg[col+1] * rsqrtf(bv[col+1] + 1e-5f);
        float sha = bbta[col]   - bm[col]  *sca;
        float shb = bbta[col+1] - bm[col+1]*scb;
        float bia = bias[col], bib = bias[col+1];
#pragma unroll
        for (int mi = 0; mi < 2; mi++) {
            int rl_lo = wm + mi*16 + gid;
#pragma unroll
            for (int h = 0; h < 2; h++) {
                int rl = rl_lo + h*8;
                Os[rl*65 + cl]     = (acc[mi][ni][2*h]   + bia)*sca + sha;
                Os[rl*65 + cl + 1] = (acc[mi][ni][2*h+1] + bib)*scb + shb;
            }
        }
    }
    __syncthreads();
    const int b = r0 >> 10;
    const int nbase = r0 & 1023;
#pragma unroll
    for (int it = 0; it < 32; it++) {
        int e = tid + it*256;     // 8192 elements
        int nl = e & 127;
        int cl = e >> 7;
        size_t o = (size_t)b*CC*NN + (size_t)(c0 + cl)*NN + (nbase + nl);
        out[o] = Os[nl*65 + cl] + x[o];
    }
}

// ---------------------------------------------------------------------------
extern "C" void kernel_launch(void* const* d_in, const int* in_sizes, int n_in,
                              void* d_out, int out_size)
{
    const float* x     = (const float*)d_in[0];
    const float* fc1_w = (const float*)d_in[1];
    const float* fc1_b = (const float*)d_in[2];
    const float* bn1_g = (const float*)d_in[3];
    const float* bn1_b = (const float*)d_in[4];
    const float* bn1_m = (const float*)d_in[5];
    const float* bn1_v = (const float*)d_in[6];
    const float* gc_w  = (const float*)d_in[7];
    const float* gc_b  = (const float*)d_in[8];
    const float* gbn_g = (const float*)d_in[9];
    const float* gbn_b = (const float*)d_in[10];
    const float* gbn_m = (const float*)d_in[11];
    const float* gbn_v = (const float*)d_in[12];
    const float* bn2_g = (const float*)d_in[13];
    const float* bn2_b = (const float*)d_in[14];
    const float* bn2_m = (const float*)d_in[15];
    const float* bn2_v = (const float*)d_in[16];
    const float* fc2_w = (const float*)d_in[17];
    const float* fc2_b = (const float*)d_in[18];
    const float* bn3_g = (const float*)d_in[19];
    const float* bn3_b = (const float*)d_in[20];
    const float* bn3_m = (const float*)d_in[21];
    const float* bn3_v = (const float*)d_in[22];
    float* out = (float*)d_out;

    // 1) fc1 + BN1 -> h (split-bf16 tensor cores)
    {
        dim3 grid(CC/64, MTOT/128);
        fc1_kernel<<<grid, 256>>>(x, fc1_w, fc1_b, bn1_g, bn1_b, bn1_m, bn1_v);
    }
    // 2) row norms
    x2_kernel<<<(MTOT*32)/256, 256>>>();
    // 3) pairwise distances (split-bf16, symmetric triangular blocks)
    {
        dim3 grid(72, 1, BB);
        dist_kernel<<<grid, 256>>>();
    }
    // 4) top-9 nearest per node (warp per row, top-2 cache + REDUX)
    topk_kernel<<<MTOT/8, 256>>>();
    // 5) MRConv + interleave (float4-vectorized, 4 nodes/block)
    {
        dim3 grid(NN/4, BB);
        mrconv_kernel<<<grid, 256>>>();
    }
    // 6) gc + gbn + bn2 + GELU (tf32 tensor cores)
    {
        dim3 grid(HID/64, MTOT/128);
        gc_kernel<<<grid, 256>>>(gc_w, gc_b, gbn_g, gbn_b, gbn_m, gbn_v,
                                 bn2_g, bn2_b, bn2_m, bn2_v);
    }
    // 7) fc2 + bn3 + residual (tf32 tensor cores)
    {
        dim3 grid(CC/64, MTOT/128);
        fc2_kernel<<<grid, 256>>>(fc2_w, fc2_b, bn3_g, bn3_b, bn3_m, bn3_v, x, out);
    }
}